// round 7
// baseline (speedup 1.0000x reference)
#include <cuda_runtime.h>
#include <cuda_bf16.h>
#include <math.h>
#include <stdint.h>

#define N_NODES 50000
#define N_EDGES 800000
#define HID     128
#define NHEAD   4
#define DH      32
#define OUTD    64

// ======================= scratch (device globals) ===========================
__device__ float g_q [N_NODES * HID];
__device__ float g_k [N_NODES * HID];
__device__ float g_v [N_NODES * HID];
__device__ float g_sk[N_NODES * HID];
__device__ float g_h [N_NODES * HID];
__device__ float g_t1[N_NODES * HID];
__device__ float g_t2[N_NODES * HID];
__device__ int   g_deg [N_NODES];
__device__ int   g_off [N_NODES + 1];
__device__ int   g_cur [N_NODES];
__device__ int   g_ssrc[N_EDGES];
__device__ float g_sattr[N_EDGES * 3];

#define SCAN_NBLK 49
__device__ int g_bsum[SCAN_NBLK];
__device__ int g_bpre[SCAN_NBLK];

__device__ __nv_bfloat16 g_xhi [N_NODES * HID];
__device__ __nv_bfloat16 g_xlo [N_NODES * HID];
__device__ __nv_bfloat16 g_hhi [N_NODES * HID];
__device__ __nv_bfloat16 g_hlo [N_NODES * HID];
__device__ __nv_bfloat16 g_t1hi[N_NODES * HID];
__device__ __nv_bfloat16 g_t1lo[N_NODES * HID];
__device__ __nv_bfloat16 g_t2hi[N_NODES * HID];
__device__ __nv_bfloat16 g_t2lo[N_NODES * HID];
__device__ __nv_bfloat16 g_whi[14 * 16384];
__device__ __nv_bfloat16 g_wlo[14 * 16384];

// ============ fused: weight split + deg zero + x split (one launch) =========
struct WPtrs { const float* p[14]; };

#define WSPLIT_BLOCKS 864           // 13*64 + 32
#define ZERO_BLOCKS   196
#define XSPLIT_BLOCKS 25000

__global__ void bigsplit_kernel(WPtrs wp, const float* __restrict__ x) {
    int b = blockIdx.x;
    if (b < WSPLIT_BLOCKS) {
        int mi, cb;
        if (b < 832) { mi = b >> 6; cb = b & 63; }
        else         { mi = 13;     cb = b - 832; }
        int i = cb * 256 + threadIdx.x;
        int n = (mi == 13) ? 8192 : 16384;
        if (i < n) {
            float v = wp.p[mi][i];
            __nv_bfloat16 h = __float2bfloat16(v);
            g_whi[mi * 16384 + i] = h;
            g_wlo[mi * 16384 + i] = __float2bfloat16(v - __bfloat162float(h));
        }
    } else if (b < WSPLIT_BLOCKS + ZERO_BLOCKS) {
        int i = (b - WSPLIT_BLOCKS) * 256 + threadIdx.x;
        if (i < N_NODES) g_deg[i] = 0;
    } else {
        int i = (b - WSPLIT_BLOCKS - ZERO_BLOCKS) * 256 + threadIdx.x;
        float v = x[i];
        __nv_bfloat16 h = __float2bfloat16(v);
        g_xhi[i] = h;
        g_xlo[i] = __float2bfloat16(v - __bfloat162float(h));
    }
}

// ======================= edge sorting =======================================
__global__ void hist_kernel(const int* __restrict__ ei) {
    int e = blockIdx.x * blockDim.x + threadIdx.x;
    if (e < N_EDGES) atomicAdd(&g_deg[ei[N_EDGES + e]], 1);
}

__global__ __launch_bounds__(1024) void scan_s1() {
    __shared__ int wsum[32];
    int tid = threadIdx.x, lane = tid & 31, wid = tid >> 5;
    int i = blockIdx.x * 1024 + tid;
    int v = (i < N_NODES) ? g_deg[i] : 0;
    int x = v;
    #pragma unroll
    for (int d = 1; d < 32; d <<= 1) {
        int y = __shfl_up_sync(0xffffffffu, x, d);
        if (lane >= d) x += y;
    }
    if (lane == 31) wsum[wid] = x;
    __syncthreads();
    if (wid == 0) {
        int s = wsum[lane];
        #pragma unroll
        for (int d = 1; d < 32; d <<= 1) {
            int y = __shfl_up_sync(0xffffffffu, s, d);
            if (lane >= d) s += y;
        }
        wsum[lane] = s;
    }
    __syncthreads();
    int incl = x + (wid > 0 ? wsum[wid - 1] : 0);
    if (i < N_NODES) g_off[i] = incl - v;
    if (tid == 1023) g_bsum[blockIdx.x] = incl;
}

// stage 2: parallel scan over 49 block sums (64 threads, 1 load each)
__global__ void scan_s2() {
    __shared__ int w0sum;
    int tid = threadIdx.x;              // 64 threads
    int lane = tid & 31, wid = tid >> 5;
    int v = (tid < SCAN_NBLK) ? g_bsum[tid] : 0;
    int x = v;
    #pragma unroll
    for (int d = 1; d < 32; d <<= 1) {
        int y = __shfl_up_sync(0xffffffffu, x, d);
        if (lane >= d) x += y;
    }
    if (wid == 0 && lane == 31) w0sum = x;
    __syncthreads();
    int incl = x + (wid ? w0sum : 0);
    if (tid < SCAN_NBLK) g_bpre[tid] = incl - v;
    if (tid == SCAN_NBLK - 1) g_off[N_NODES] = incl;
}

__global__ void scan_s3() {
    int i = blockIdx.x * blockDim.x + threadIdx.x;
    if (i < N_NODES) {
        int o = g_off[i] + g_bpre[i >> 10];
        g_off[i] = o;
        g_cur[i] = o;
    }
}

__global__ void scatter_kernel(const int* __restrict__ ei, const float* __restrict__ attr) {
    int e = blockIdx.x * blockDim.x + threadIdx.x;
    if (e < N_EDGES) {
        int dst = ei[N_EDGES + e];
        int pos = atomicAdd(&g_cur[dst], 1);
        g_ssrc[pos] = ei[e];
        g_sattr[3 * pos + 0] = attr[3 * e + 0];
        g_sattr[3 * pos + 1] = attr[3 * e + 1];
        g_sattr[3 * pos + 2] = attr[3 * e + 2];
    }
}

// ======================= GELU ==============================================
__device__ __forceinline__ float gelu_f(float x) {
    float x3 = x * x * x;
    float u = 0.7978845608028654f * (x + 0.044715f * x3);
    return 0.5f * x * (1.0f + tanhf(u));
}

// ======================= HMMA mma.sync GEMM (32x64 warp tiles) ==============
#define SROW 136
#define OFF_AH 0
#define OFF_AL 34816
#define OFF_BH 69632
#define OFF_BL 104448
#define MMA_SMEM 139264

__device__ __forceinline__ uint32_t lds32(const __nv_bfloat16* p) {
    return *(const uint32_t*)p;
}

__device__ __forceinline__ void mma16816(float* c,
    uint32_t a0, uint32_t a1, uint32_t a2, uint32_t a3,
    uint32_t b0, uint32_t b1) {
    asm volatile(
        "mma.sync.aligned.m16n8k16.row.col.f32.bf16.bf16.f32 "
        "{%0,%1,%2,%3}, {%4,%5,%6,%7}, {%8,%9}, {%0,%1,%2,%3};"
        : "+f"(c[0]), "+f"(c[1]), "+f"(c[2]), "+f"(c[3])
        : "r"(a0), "r"(a1), "r"(a2), "r"(a3), "r"(b0), "r"(b1));
}

// stage A: 128 rows x 16 uint4 with 256 threads (2 threads/row, 8 uint4 each)
__device__ __forceinline__ void gemm_stage_A(
    const __nv_bfloat16* Ahi, const __nv_bfloat16* Alo,
    __nv_bfloat16* sAh, __nv_bfloat16* sAl, int m0, int M, int tid)
{
    int row = tid >> 1;
    int u0  = (tid & 1) * 8;
    int gr  = m0 + row;
    bool ok = gr < M;
    const uint4* ah = (const uint4*)(Ahi + (size_t)gr * 128);
    const uint4* al = (const uint4*)(Alo + (size_t)gr * 128);
    uint4 z = make_uint4(0u, 0u, 0u, 0u);
    #pragma unroll
    for (int u = u0; u < u0 + 8; u++) {
        *(uint4*)(&sAh[row * SROW + u * 8]) = ok ? ah[u] : z;
        *(uint4*)(&sAl[row * SROW + u * 8]) = ok ? al[u] : z;
    }
}

__device__ __forceinline__ void gemm_stage_B(
    const __nv_bfloat16* Bhi, const __nv_bfloat16* Blo,
    __nv_bfloat16* sBh, __nv_bfloat16* sBl, int Nout, int tid)
{
    if (Nout == 128) {
        int row = tid >> 1;
        int u0  = (tid & 1) * 8;
        const uint4* bh = (const uint4*)(Bhi + (size_t)row * 128);
        const uint4* bl = (const uint4*)(Blo + (size_t)row * 128);
        #pragma unroll
        for (int u = u0; u < u0 + 8; u++) {
            *(uint4*)(&sBh[row * SROW + u * 8]) = bh[u];
            *(uint4*)(&sBl[row * SROW + u * 8]) = bl[u];
        }
    } else {                              // Nout == 64
        int row = tid >> 2;
        int u0  = (tid & 3) * 4;
        const uint4* bh = (const uint4*)(Bhi + (size_t)row * 128);
        const uint4* bl = (const uint4*)(Blo + (size_t)row * 128);
        #pragma unroll
        for (int u = u0; u < u0 + 4; u++) {
            *(uint4*)(&sBh[row * SROW + u * 8]) = bh[u];
            *(uint4*)(&sBl[row * SROW + u * 8]) = bl[u];
        }
    }
}

// 32x64 warp tile: 2 m-tiles x up-to-8 n-tiles, 3 hi/lo passes
__device__ __forceinline__ void gemm_mainloop(
    const __nv_bfloat16* sAh, const __nv_bfloat16* sAl,
    const __nv_bfloat16* sBh, const __nv_bfloat16* sBl,
    float acc[2][8][4], int mt, int grp, int qd, int ntBeg, int ntN)
{
    for (int kt = 0; kt < 128; kt += 16) {
        uint32_t ah[2][4], al[2][4];
        #pragma unroll
        for (int mi = 0; mi < 2; mi++) {
            int aoff = (mt + mi * 16 + grp) * SROW + kt + 2 * qd;
            ah[mi][0] = lds32(sAh + aoff);
            ah[mi][1] = lds32(sAh + aoff + 8 * SROW);
            ah[mi][2] = lds32(sAh + aoff + 8);
            ah[mi][3] = lds32(sAh + aoff + 8 * SROW + 8);
            al[mi][0] = lds32(sAl + aoff);
            al[mi][1] = lds32(sAl + aoff + 8 * SROW);
            al[mi][2] = lds32(sAl + aoff + 8);
            al[mi][3] = lds32(sAl + aoff + 8 * SROW + 8);
        }
        #pragma unroll
        for (int t = 0; t < 8; t++) {
            if (t >= ntN) break;
            int boff = ((ntBeg + t) * 8 + grp) * SROW + kt + 2 * qd;
            uint32_t bh0 = lds32(sBh + boff);
            uint32_t bh1 = lds32(sBh + boff + 8);
            uint32_t bl0 = lds32(sBl + boff);
            uint32_t bl1 = lds32(sBl + boff + 8);
            #pragma unroll
            for (int mi = 0; mi < 2; mi++) {
                mma16816(acc[mi][t], ah[mi][0], ah[mi][1], ah[mi][2], ah[mi][3], bh0, bh1);
                mma16816(acc[mi][t], ah[mi][0], ah[mi][1], ah[mi][2], ah[mi][3], bl0, bl1);
                mma16816(acc[mi][t], al[mi][0], al[mi][1], al[mi][2], al[mi][3], bh0, bh1);
            }
        }
    }
}

__global__ __launch_bounds__(256, 1) void mma_gemm(
    const __nv_bfloat16* __restrict__ Ahi, const __nv_bfloat16* __restrict__ Alo,
    const __nv_bfloat16* __restrict__ Bhi, const __nv_bfloat16* __restrict__ Blo,
    const float* __restrict__ bias, const float* __restrict__ res,
    float* __restrict__ C, __nv_bfloat16* __restrict__ Chi, __nv_bfloat16* __restrict__ Clo,
    int M, int Nout, int act)
{
    extern __shared__ char smem[];
    __nv_bfloat16* sAh = (__nv_bfloat16*)(smem + OFF_AH);
    __nv_bfloat16* sAl = (__nv_bfloat16*)(smem + OFF_AL);
    __nv_bfloat16* sBh = (__nv_bfloat16*)(smem + OFF_BH);
    __nv_bfloat16* sBl = (__nv_bfloat16*)(smem + OFF_BL);
    int tid = threadIdx.x;
    int m0 = blockIdx.x * 128;

    gemm_stage_A(Ahi, Alo, sAh, sAl, m0, M, tid);
    gemm_stage_B(Bhi, Blo, sBh, sBl, Nout, tid);
    __syncthreads();

    int lane = tid & 31, wid = tid >> 5;
    int grp = lane >> 2, qd = lane & 3;
    int mt = (wid >> 1) * 32;             // 4 m-warps x 32 rows
    int NT = Nout >> 3;
    int ntBeg = (wid & 1) * (NT >> 1);
    int ntN   = NT >> 1;                  // 8 (Nout=128) or 4 (Nout=64)

    float acc[2][8][4];
    #pragma unroll
    for (int mi = 0; mi < 2; mi++)
        #pragma unroll
        for (int i = 0; i < 8; i++)
            #pragma unroll
            for (int j = 0; j < 4; j++) acc[mi][i][j] = 0.f;

    gemm_mainloop(sAh, sAl, sBh, sBl, acc, mt, grp, qd, ntBeg, ntN);

    #pragma unroll
    for (int mi = 0; mi < 2; mi++) {
        #pragma unroll
        for (int t = 0; t < 8; t++) {
            if (t >= ntN) break;
            int col = (ntBeg + t) * 8 + 2 * qd;
            float bsum0 = bias ? bias[col]     : 0.f;
            float bsum1 = bias ? bias[col + 1] : 0.f;
            #pragma unroll
            for (int half = 0; half < 2; half++) {
                int row = m0 + mt + mi * 16 + grp + half * 8;
                if (row >= M) continue;
                float v0 = acc[mi][t][half * 2 + 0] + bsum0;
                float v1 = acc[mi][t][half * 2 + 1] + bsum1;
                if (act) { v0 = gelu_f(v0); v1 = gelu_f(v1); }
                size_t base = (size_t)row * Nout + col;
                if (res) { v0 += res[base]; v1 += res[base + 1]; }
                *(float2*)(C + base) = make_float2(v0, v1);
                if (Chi) {
                    __nv_bfloat16 h0 = __float2bfloat16(v0);
                    __nv_bfloat16 h1 = __float2bfloat16(v1);
                    __nv_bfloat162 hh; hh.x = h0; hh.y = h1;
                    __nv_bfloat162 ll;
                    ll.x = __float2bfloat16(v0 - __bfloat162float(h0));
                    ll.y = __float2bfloat16(v1 - __bfloat162float(h1));
                    *(__nv_bfloat162*)(Chi + base) = hh;
                    *(__nv_bfloat162*)(Clo + base) = ll;
                }
            }
        }
    }
}

struct QkvsPtrs {
    const __nv_bfloat16 *bh[4], *bl[4];
    float* c[4];
};

__global__ __launch_bounds__(256, 1) void qkvs_gemm(
    const __nv_bfloat16* __restrict__ Ahi, const __nv_bfloat16* __restrict__ Alo,
    QkvsPtrs pp, int M)
{
    extern __shared__ char smem[];
    __nv_bfloat16* sAh = (__nv_bfloat16*)(smem + OFF_AH);
    __nv_bfloat16* sAl = (__nv_bfloat16*)(smem + OFF_AL);
    __nv_bfloat16* sBh = (__nv_bfloat16*)(smem + OFF_BH);
    __nv_bfloat16* sBl = (__nv_bfloat16*)(smem + OFF_BL);
    int tid = threadIdx.x;
    int m0 = blockIdx.x * 128;
    int sel = blockIdx.y;

    gemm_stage_A(Ahi, Alo, sAh, sAl, m0, M, tid);
    gemm_stage_B(pp.bh[sel], pp.bl[sel], sBh, sBl, HID, tid);
    __syncthreads();

    int lane = tid & 31, wid = tid >> 5;
    int grp = lane >> 2, qd = lane & 3;
    int mt = (wid >> 1) * 32;
    int ntBeg = (wid & 1) * 8;

    float acc[2][8][4];
    #pragma unroll
    for (int mi = 0; mi < 2; mi++)
        #pragma unroll
        for (int i = 0; i < 8; i++)
            #pragma unroll
            for (int j = 0; j < 4; j++) acc[mi][i][j] = 0.f;

    gemm_mainloop(sAh, sAl, sBh, sBl, acc, mt, grp, qd, ntBeg, 8);

    float* C = pp.c[sel];
    #pragma unroll
    for (int mi = 0; mi < 2; mi++) {
        #pragma unroll
        for (int t = 0; t < 8; t++) {
            int col = (ntBeg + t) * 8 + 2 * qd;
            #pragma unroll
            for (int half = 0; half < 2; half++) {
                int row = m0 + mt + mi * 16 + grp + half * 8;
                if (row >= M) continue;
                size_t base = (size_t)row * HID + col;
                *(float2*)(C + base) = make_float2(acc[mi][t][half * 2], acc[mi][t][half * 2 + 1]);
            }
        }
    }
}

// ======================= edge attention (simple loop, reg We) ===============
__global__ __launch_bounds__(128) void attn_kernel(
    const float* __restrict__ q, const float* __restrict__ k,
    const float* __restrict__ v, const float* __restrict__ skip,
    const float* __restrict__ We, float* __restrict__ out,
    __nv_bfloat16* __restrict__ outhi, __nv_bfloat16* __restrict__ outlo)
{
    __shared__ float we_s[HID * 3];
    int tid = threadIdx.x;
    for (int i = tid; i < HID * 3; i += blockDim.x) we_s[i] = We[i];
    __syncthreads();

    int warp = blockIdx.x * (blockDim.x >> 5) + (tid >> 5);
    if (warp >= N_NODES) return;
    int lane = tid & 31;
    int col  = (lane >> 3) * DH + (lane & 7) * 4;

    float wr[12];
    #pragma unroll
    for (int i = 0; i < 4; i++)
        #pragma unroll
        for (int c = 0; c < 3; c++)
            wr[i * 3 + c] = we_s[3 * (col + i) + c];

    float4 qv = *(const float4*)(q + (size_t)warp * HID + col);
    float m = -INFINITY, ssum = 0.f;
    float ox = 0.f, oy = 0.f, oz = 0.f, ow = 0.f;

    int e0 = g_off[warp], e1 = g_off[warp + 1];
    for (int e = e0; e < e1; e++) {
        int src = g_ssrc[e];
        float a0 = g_sattr[3 * e + 0];
        float a1 = g_sattr[3 * e + 1];
        float a2 = g_sattr[3 * e + 2];
        float4 kv = *(const float4*)(k + (size_t)src * HID + col);
        float4 vv = *(const float4*)(v + (size_t)src * HID + col);
        float ec0 = fmaf(a0, wr[0], fmaf(a1, wr[1],  a2 * wr[2]));
        float ec1 = fmaf(a0, wr[3], fmaf(a1, wr[4],  a2 * wr[5]));
        float ec2 = fmaf(a0, wr[6], fmaf(a1, wr[7],  a2 * wr[8]));
        float ec3 = fmaf(a0, wr[9], fmaf(a1, wr[10], a2 * wr[11]));
        float kx = kv.x + ec0, ky = kv.y + ec1, kz = kv.z + ec2, kw = kv.w + ec3;
        float dot = qv.x * kx + qv.y * ky + qv.z * kz + qv.w * kw;
        dot += __shfl_xor_sync(0xffffffffu, dot, 1);
        dot += __shfl_xor_sync(0xffffffffu, dot, 2);
        dot += __shfl_xor_sync(0xffffffffu, dot, 4);
        float alpha = dot * 0.17677669529663687f;
        float nm = fmaxf(m, alpha);
        float sc = __expf(m - nm);
        float p  = __expf(alpha - nm);
        ssum = ssum * sc + p;
        ox = ox * sc + p * (vv.x + ec0);
        oy = oy * sc + p * (vv.y + ec1);
        oz = oz * sc + p * (vv.z + ec2);
        ow = ow * sc + p * (vv.w + ec3);
        m = nm;
    }
    float inv = 1.0f / fmaxf(ssum, 1e-16f);
    float4 sk = *(const float4*)(skip + (size_t)warp * HID + col);
    float o0 = ox * inv + sk.x, o1 = oy * inv + sk.y;
    float o2 = oz * inv + sk.z, o3 = ow * inv + sk.w;
    size_t base = (size_t)warp * HID + col;
    *(float4*)(out + base) = make_float4(o0, o1, o2, o3);

    float vs[4] = {o0, o1, o2, o3};
    #pragma unroll
    for (int pr = 0; pr < 2; pr++) {
        float v0 = vs[pr * 2], v1 = vs[pr * 2 + 1];
        __nv_bfloat16 h0 = __float2bfloat16(v0);
        __nv_bfloat16 h1 = __float2bfloat16(v1);
        __nv_bfloat162 hh; hh.x = h0; hh.y = h1;
        __nv_bfloat162 ll;
        ll.x = __float2bfloat16(v0 - __bfloat162float(h0));
        ll.y = __float2bfloat16(v1 - __bfloat162float(h1));
        *(__nv_bfloat162*)(outhi + base + pr * 2) = hh;
        *(__nv_bfloat162*)(outlo + base + pr * 2) = ll;
    }
}

// ======================= launch =============================================
static inline void run_mm(cudaStream_t s,
                          const __nv_bfloat16* Ahi, const __nv_bfloat16* Alo,
                          const __nv_bfloat16* Bhi, const __nv_bfloat16* Blo,
                          const float* bias, const float* res,
                          float* C, __nv_bfloat16* Chi, __nv_bfloat16* Clo,
                          int M, int Nout, int act) {
    int grid = (M + 127) / 128;
    mma_gemm<<<grid, 256, MMA_SMEM, s>>>(Ahi, Alo, Bhi, Blo, bias, res, C, Chi, Clo, M, Nout, act);
}

extern "C" void kernel_launch(void* const* d_in, const int* in_sizes, int n_in,
                              void* d_out, int out_size) {
    const float* x    = (const float*)d_in[0];
    const int*   ei   = (const int*)  d_in[1];
    const float* attr = (const float*)d_in[2];
    const float* Wq1 = (const float*)d_in[3],  *Wk1 = (const float*)d_in[4];
    const float* Wv1 = (const float*)d_in[5],  *We1 = (const float*)d_in[6];
    const float* Ws1 = (const float*)d_in[7];
    const float* M1a = (const float*)d_in[8],  *b1a = (const float*)d_in[9];
    const float* M1b = (const float*)d_in[10], *b1b = (const float*)d_in[11];
    const float* Wq2 = (const float*)d_in[12], *Wk2 = (const float*)d_in[13];
    const float* Wv2 = (const float*)d_in[14], *We2 = (const float*)d_in[15];
    const float* Ws2 = (const float*)d_in[16];
    const float* M2a = (const float*)d_in[17], *b2a = (const float*)d_in[18];
    const float* M2b = (const float*)d_in[19], *b2b = (const float*)d_in[20];
    const float* Wf1 = (const float*)d_in[21], *bf1 = (const float*)d_in[22];
    const float* Wf2 = (const float*)d_in[23], *bf2 = (const float*)d_in[24];
    float* out = (float*)d_out;

    float *q, *k, *v, *sk, *h, *t1, *t2;
    cudaGetSymbolAddress((void**)&q,  g_q);
    cudaGetSymbolAddress((void**)&k,  g_k);
    cudaGetSymbolAddress((void**)&v,  g_v);
    cudaGetSymbolAddress((void**)&sk, g_sk);
    cudaGetSymbolAddress((void**)&h,  g_h);
    cudaGetSymbolAddress((void**)&t1, g_t1);
    cudaGetSymbolAddress((void**)&t2, g_t2);

    __nv_bfloat16 *xhi, *xlo, *hhi, *hlo, *t1hi, *t1lo, *t2hi, *t2lo, *whi, *wlo;
    cudaGetSymbolAddress((void**)&xhi,  g_xhi);
    cudaGetSymbolAddress((void**)&xlo,  g_xlo);
    cudaGetSymbolAddress((void**)&hhi,  g_hhi);
    cudaGetSymbolAddress((void**)&hlo,  g_hlo);
    cudaGetSymbolAddress((void**)&t1hi, g_t1hi);
    cudaGetSymbolAddress((void**)&t1lo, g_t1lo);
    cudaGetSymbolAddress((void**)&t2hi, g_t2hi);
    cudaGetSymbolAddress((void**)&t2lo, g_t2lo);
    cudaGetSymbolAddress((void**)&whi,  g_whi);
    cudaGetSymbolAddress((void**)&wlo,  g_wlo);

    cudaFuncSetAttribute(mma_gemm,  cudaFuncAttributeMaxDynamicSharedMemorySize, MMA_SMEM);
    cudaFuncSetAttribute(qkvs_gemm, cudaFuncAttributeMaxDynamicSharedMemorySize, MMA_SMEM);

    cudaStream_t s = 0;
    #define WHI(i) (whi + (i) * 16384)
    #define WLO(i) (wlo + (i) * 16384)

    int gblocks = (N_NODES + 127) / 128;
    int ablocks = (N_NODES * 32 + 127) / 128;

    // 1: all splits + deg zero
    WPtrs wp;
    const float* wsrc[14] = {Wq1, Wk1, Wv1, Ws1, M1a, M1b, Wq2, Wk2, Wv2, Ws2, M2a, M2b, Wf1, Wf2};
    for (int i = 0; i < 14; i++) wp.p[i] = wsrc[i];
    bigsplit_kernel<<<WSPLIT_BLOCKS + ZERO_BLOCKS + XSPLIT_BLOCKS, 256, 0, s>>>(wp, x);
    // 2: hist
    hist_kernel<<<(N_EDGES + 255) / 256, 256, 0, s>>>(ei);
    // 3: scan stage 1
    scan_s1<<<SCAN_NBLK, 1024, 0, s>>>();
    // 4: layer-1 fused QKVS GEMM  (ncu capture slot)
    QkvsPtrs p1;
    for (int i = 0; i < 4; i++) { p1.bh[i] = WHI(i); p1.bl[i] = WLO(i); }
    p1.c[0] = q; p1.c[1] = k; p1.c[2] = v; p1.c[3] = sk;
    qkvs_gemm<<<dim3(gblocks, 4), 256, MMA_SMEM, s>>>(xhi, xlo, p1, N_NODES);
    // 5-6: scan stages 2,3
    scan_s2<<<1, 64, 0, s>>>();
    scan_s3<<<(N_NODES + 255) / 256, 256, 0, s>>>();
    // 7: scatter
    scatter_kernel<<<(N_EDGES + 255) / 256, 256, 0, s>>>(ei, attr);

    // layer 1
    attn_kernel<<<ablocks, 128, 0, s>>>(q, k, v, sk, We1, h, hhi, hlo);
    run_mm(s, hhi,  hlo,  WHI(4), WLO(4), b1a, nullptr, t1, t1hi, t1lo, N_NODES, HID, 1);
    run_mm(s, t1hi, t1lo, WHI(5), WLO(5), b1b, h,       t2, t2hi, t2lo, N_NODES, HID, 1);

    // layer 2
    QkvsPtrs p2;
    for (int i = 0; i < 4; i++) { p2.bh[i] = WHI(6 + i); p2.bl[i] = WLO(6 + i); }
    p2.c[0] = q; p2.c[1] = k; p2.c[2] = v; p2.c[3] = sk;
    qkvs_gemm<<<dim3(gblocks, 4), 256, MMA_SMEM, s>>>(t2hi, t2lo, p2, N_NODES);
    attn_kernel<<<ablocks, 128, 0, s>>>(q, k, v, sk, We2, h, hhi, hlo);
    run_mm(s, hhi,  hlo,  WHI(10), WLO(10), b2a, nullptr, t1, t1hi, t1lo, N_NODES, HID, 1);
    run_mm(s, t1hi, t1lo, WHI(11), WLO(11), b2b, h,       t2, t2hi, t2lo, N_NODES, HID, 1);

    // final MLP
    run_mm(s, t2hi, t2lo, WHI(12), WLO(12), bf1, nullptr, t1, t1hi, t1lo, N_NODES, HID, 1);
    run_mm(s, t1hi, t1lo, WHI(13), WLO(13), bf2, nullptr, out, nullptr, nullptr, N_NODES, OUTD, 1);
}

// round 8
// speedup vs baseline: 1.1761x; 1.1761x over previous
#include <cuda_runtime.h>
#include <cuda_bf16.h>
#include <math.h>
#include <stdint.h>

#define N_NODES 50000
#define N_EDGES 800000
#define HID     128
#define NHEAD   4
#define DH      32
#define OUTD    64

// ======================= scratch (device globals) ===========================
__device__ float g_q [N_NODES * HID];
__device__ float g_k [N_NODES * HID];
__device__ float g_v [N_NODES * HID];
__device__ float g_sk[N_NODES * HID];
__device__ float g_h [N_NODES * HID];
__device__ float g_t1[N_NODES * HID];
__device__ float g_t2[N_NODES * HID];
__device__ int   g_deg [N_NODES];
__device__ int   g_off [N_NODES + 1];
__device__ int   g_cur [N_NODES];
__device__ int   g_ssrc[N_EDGES];
__device__ float g_sattr[N_EDGES * 3];

#define SCAN_NBLK 49
__device__ int g_bsum[SCAN_NBLK];
__device__ int g_bpre[SCAN_NBLK];

__device__ __nv_bfloat16 g_xhi [N_NODES * HID];
__device__ __nv_bfloat16 g_xlo [N_NODES * HID];
__device__ __nv_bfloat16 g_hhi [N_NODES * HID];
__device__ __nv_bfloat16 g_hlo [N_NODES * HID];
__device__ __nv_bfloat16 g_t1hi[N_NODES * HID];
__device__ __nv_bfloat16 g_t1lo[N_NODES * HID];
__device__ __nv_bfloat16 g_t2hi[N_NODES * HID];
__device__ __nv_bfloat16 g_t2lo[N_NODES * HID];
__device__ __nv_bfloat16 g_whi[14 * 16384];
__device__ __nv_bfloat16 g_wlo[14 * 16384];

// ============ fused: weight split + deg zero + x split (one launch) =========
struct WPtrs { const float* p[14]; };

#define WSPLIT_BLOCKS 864
#define ZERO_BLOCKS   196
#define XSPLIT_BLOCKS 25000

__global__ void bigsplit_kernel(WPtrs wp, const float* __restrict__ x) {
    int b = blockIdx.x;
    if (b < WSPLIT_BLOCKS) {
        int mi, cb;
        if (b < 832) { mi = b >> 6; cb = b & 63; }
        else         { mi = 13;     cb = b - 832; }
        int i = cb * 256 + threadIdx.x;
        int n = (mi == 13) ? 8192 : 16384;
        if (i < n) {
            float v = wp.p[mi][i];
            __nv_bfloat16 h = __float2bfloat16(v);
            g_whi[mi * 16384 + i] = h;
            g_wlo[mi * 16384 + i] = __float2bfloat16(v - __bfloat162float(h));
        }
    } else if (b < WSPLIT_BLOCKS + ZERO_BLOCKS) {
        int i = (b - WSPLIT_BLOCKS) * 256 + threadIdx.x;
        if (i < N_NODES) g_deg[i] = 0;
    } else {
        int i = (b - WSPLIT_BLOCKS - ZERO_BLOCKS) * 256 + threadIdx.x;
        float v = x[i];
        __nv_bfloat16 h = __float2bfloat16(v);
        g_xhi[i] = h;
        g_xlo[i] = __float2bfloat16(v - __bfloat162float(h));
    }
}

// ======================= edge sorting =======================================
__global__ void hist_kernel(const int* __restrict__ ei) {
    int e = blockIdx.x * blockDim.x + threadIdx.x;
    if (e < N_EDGES) atomicAdd(&g_deg[ei[N_EDGES + e]], 1);
}

__global__ __launch_bounds__(1024) void scan_s1() {
    __shared__ int wsum[32];
    int tid = threadIdx.x, lane = tid & 31, wid = tid >> 5;
    int i = blockIdx.x * 1024 + tid;
    int v = (i < N_NODES) ? g_deg[i] : 0;
    int x = v;
    #pragma unroll
    for (int d = 1; d < 32; d <<= 1) {
        int y = __shfl_up_sync(0xffffffffu, x, d);
        if (lane >= d) x += y;
    }
    if (lane == 31) wsum[wid] = x;
    __syncthreads();
    if (wid == 0) {
        int s = wsum[lane];
        #pragma unroll
        for (int d = 1; d < 32; d <<= 1) {
            int y = __shfl_up_sync(0xffffffffu, s, d);
            if (lane >= d) s += y;
        }
        wsum[lane] = s;
    }
    __syncthreads();
    int incl = x + (wid > 0 ? wsum[wid - 1] : 0);
    if (i < N_NODES) g_off[i] = incl - v;
    if (tid == 1023) g_bsum[blockIdx.x] = incl;
}

__global__ void scan_s2() {
    __shared__ int w0sum;
    int tid = threadIdx.x;
    int lane = tid & 31, wid = tid >> 5;
    int v = (tid < SCAN_NBLK) ? g_bsum[tid] : 0;
    int x = v;
    #pragma unroll
    for (int d = 1; d < 32; d <<= 1) {
        int y = __shfl_up_sync(0xffffffffu, x, d);
        if (lane >= d) x += y;
    }
    if (wid == 0 && lane == 31) w0sum = x;
    __syncthreads();
    int incl = x + (wid ? w0sum : 0);
    if (tid < SCAN_NBLK) g_bpre[tid] = incl - v;
    if (tid == SCAN_NBLK - 1) g_off[N_NODES] = incl;
}

__global__ void scan_s3() {
    int i = blockIdx.x * blockDim.x + threadIdx.x;
    if (i < N_NODES) {
        int o = g_off[i] + g_bpre[i >> 10];
        g_off[i] = o;
        g_cur[i] = o;
    }
}

__global__ void scatter_kernel(const int* __restrict__ ei, const float* __restrict__ attr) {
    int e = blockIdx.x * blockDim.x + threadIdx.x;
    if (e < N_EDGES) {
        int dst = ei[N_EDGES + e];
        int pos = atomicAdd(&g_cur[dst], 1);
        g_ssrc[pos] = ei[e];
        g_sattr[3 * pos + 0] = attr[3 * e + 0];
        g_sattr[3 * pos + 1] = attr[3 * e + 1];
        g_sattr[3 * pos + 2] = attr[3 * e + 2];
    }
}

// ======================= GELU ==============================================
__device__ __forceinline__ float gelu_f(float x) {
    float x3 = x * x * x;
    float u = 0.7978845608028654f * (x + 0.044715f * x3);
    return 0.5f * x * (1.0f + tanhf(u));
}

// ======================= HMMA mma.sync GEMM (ldmatrix frags) ================
#define SROW 136
#define OFF_AH 0
#define OFF_AL 34816
#define OFF_BH 69632
#define OFF_BL 104448
#define MMA_SMEM 139264

__device__ __forceinline__ void mma16816(float* c,
    uint32_t a0, uint32_t a1, uint32_t a2, uint32_t a3,
    uint32_t b0, uint32_t b1) {
    asm volatile(
        "mma.sync.aligned.m16n8k16.row.col.f32.bf16.bf16.f32 "
        "{%0,%1,%2,%3}, {%4,%5,%6,%7}, {%8,%9}, {%0,%1,%2,%3};"
        : "+f"(c[0]), "+f"(c[1]), "+f"(c[2]), "+f"(c[3])
        : "r"(a0), "r"(a1), "r"(a2), "r"(a3), "r"(b0), "r"(b1));
}

__device__ __forceinline__ void ldsm_x4(uint32_t& r0, uint32_t& r1,
                                        uint32_t& r2, uint32_t& r3, uint32_t addr) {
    asm volatile("ldmatrix.sync.aligned.m8n8.x4.shared.b16 {%0,%1,%2,%3}, [%4];"
                 : "=r"(r0), "=r"(r1), "=r"(r2), "=r"(r3) : "r"(addr));
}

__device__ __forceinline__ uint32_t smem_u32(const void* p) {
    return (uint32_t)__cvta_generic_to_shared(p);
}

// stage A (512 threads: 4 threads/row, 4 uint4 each)
__device__ __forceinline__ void gemm_stage_A(
    const __nv_bfloat16* Ahi, const __nv_bfloat16* Alo,
    __nv_bfloat16* sAh, __nv_bfloat16* sAl, int m0, int M, int tid)
{
    int row = tid >> 2;
    int u0  = (tid & 3) * 4;
    int gr  = m0 + row;
    bool ok = gr < M;
    const uint4* ah = (const uint4*)(Ahi + (size_t)gr * 128);
    const uint4* al = (const uint4*)(Alo + (size_t)gr * 128);
    uint4 z = make_uint4(0u, 0u, 0u, 0u);
    #pragma unroll
    for (int u = u0; u < u0 + 4; u++) {
        *(uint4*)(&sAh[row * SROW + u * 8]) = ok ? ah[u] : z;
        *(uint4*)(&sAl[row * SROW + u * 8]) = ok ? al[u] : z;
    }
}

__device__ __forceinline__ void gemm_stage_B(
    const __nv_bfloat16* Bhi, const __nv_bfloat16* Blo,
    __nv_bfloat16* sBh, __nv_bfloat16* sBl, int Nout, int tid)
{
    if (tid < Nout * 4) {
        int row = tid >> 2;
        int u0  = (tid & 3) * 4;
        const uint4* bh = (const uint4*)(Bhi + (size_t)row * 128);
        const uint4* bl = (const uint4*)(Blo + (size_t)row * 128);
        #pragma unroll
        for (int u = u0; u < u0 + 4; u++) {
            *(uint4*)(&sBh[row * SROW + u * 8]) = bh[u];
            *(uint4*)(&sBl[row * SROW + u * 8]) = bl[u];
        }
    }
}

// mainloop: 16x64(or 32) warp tile, fragments via ldmatrix.x4
// ntN must be even (8 for Nout=128, 4 for Nout=64).
__device__ __forceinline__ void gemm_mainloop(
    const __nv_bfloat16* sAh, const __nv_bfloat16* sAl,
    const __nv_bfloat16* sBh, const __nv_bfloat16* sBl,
    float acc[8][4], int mt, int lane, int ntBeg, int ntN)
{
    uint32_t aAh = smem_u32(sAh), aAl = smem_u32(sAl);
    uint32_t aBh = smem_u32(sBh), aBl = smem_u32(sBl);
    // A lane offset: rows mt + (lane&15), k-half 8*(lane>>4)
    int aoff = (mt + (lane & 15)) * SROW + 8 * (lane >> 4);
    // B lane offset per nt-pair p: nt = ntBeg+2p+(lane>>4), row-in-nt = lane&7,
    // k-half = 8*((lane>>3)&1)
    int brow = (lane & 7);
    int bsel = (lane >> 4);          // which nt of the pair
    int bk   = 8 * ((lane >> 3) & 1);

    for (int kt = 0; kt < 128; kt += 16) {
        uint32_t ah0, ah1, ah2, ah3, al0, al1, al2, al3;
        ldsm_x4(ah0, ah1, ah2, ah3, aAh + (uint32_t)(aoff + kt) * 2);
        ldsm_x4(al0, al1, al2, al3, aAl + (uint32_t)(aoff + kt) * 2);
        #pragma unroll
        for (int p = 0; p < 4; p++) {
            if (2 * p >= ntN) break;
            int nt = ntBeg + 2 * p + bsel;
            int boff = (nt * 8 + brow) * SROW + bk + kt;
            uint32_t bh0, bh1, bh2, bh3, bl0, bl1, bl2, bl3;
            ldsm_x4(bh0, bh1, bh2, bh3, aBh + (uint32_t)boff * 2);
            ldsm_x4(bl0, bl1, bl2, bl3, aBl + (uint32_t)boff * 2);
            // regs: {b0,b1} for nt=ntBeg+2p, {b2,b3} for nt=ntBeg+2p+1
            mma16816(acc[2 * p + 0], ah0, ah1, ah2, ah3, bh0, bh1);
            mma16816(acc[2 * p + 0], ah0, ah1, ah2, ah3, bl0, bl1);
            mma16816(acc[2 * p + 0], al0, al1, al2, al3, bh0, bh1);
            mma16816(acc[2 * p + 1], ah0, ah1, ah2, ah3, bh2, bh3);
            mma16816(acc[2 * p + 1], ah0, ah1, ah2, ah3, bl2, bl3);
            mma16816(acc[2 * p + 1], al0, al1, al2, al3, bh2, bh3);
        }
    }
}

__global__ __launch_bounds__(512, 1) void mma_gemm(
    const __nv_bfloat16* __restrict__ Ahi, const __nv_bfloat16* __restrict__ Alo,
    const __nv_bfloat16* __restrict__ Bhi, const __nv_bfloat16* __restrict__ Blo,
    const float* __restrict__ bias, const float* __restrict__ res,
    float* __restrict__ C, __nv_bfloat16* __restrict__ Chi, __nv_bfloat16* __restrict__ Clo,
    int M, int Nout, int act)
{
    extern __shared__ char smem[];
    __nv_bfloat16* sAh = (__nv_bfloat16*)(smem + OFF_AH);
    __nv_bfloat16* sAl = (__nv_bfloat16*)(smem + OFF_AL);
    __nv_bfloat16* sBh = (__nv_bfloat16*)(smem + OFF_BH);
    __nv_bfloat16* sBl = (__nv_bfloat16*)(smem + OFF_BL);
    int tid = threadIdx.x;
    int m0 = blockIdx.x * 128;

    gemm_stage_A(Ahi, Alo, sAh, sAl, m0, M, tid);
    gemm_stage_B(Bhi, Blo, sBh, sBl, Nout, tid);
    __syncthreads();

    int lane = tid & 31, wid = tid >> 5;
    int grp = lane >> 2, qd = lane & 3;
    int mt = (wid >> 1) * 16;
    int NT = Nout >> 3;
    int ntBeg = (wid & 1) * (NT >> 1);
    int ntN   = NT >> 1;

    float acc[8][4];
    #pragma unroll
    for (int i = 0; i < 8; i++)
        #pragma unroll
        for (int j = 0; j < 4; j++) acc[i][j] = 0.f;

    gemm_mainloop(sAh, sAl, sBh, sBl, acc, mt, lane, ntBeg, ntN);

    #pragma unroll
    for (int t = 0; t < 8; t++) {
        if (t >= ntN) break;
        int nt = ntBeg + t;
        int col = nt * 8 + 2 * qd;
        float bsum0 = bias ? bias[col]     : 0.f;
        float bsum1 = bias ? bias[col + 1] : 0.f;
        #pragma unroll
        for (int half = 0; half < 2; half++) {
            int row = m0 + mt + grp + half * 8;
            if (row >= M) continue;
            float v0 = acc[t][half * 2 + 0] + bsum0;
            float v1 = acc[t][half * 2 + 1] + bsum1;
            if (act) { v0 = gelu_f(v0); v1 = gelu_f(v1); }
            size_t base = (size_t)row * Nout + col;
            if (res) { v0 += res[base]; v1 += res[base + 1]; }
            *(float2*)(C + base) = make_float2(v0, v1);
            if (Chi) {
                __nv_bfloat16 h0 = __float2bfloat16(v0);
                __nv_bfloat16 h1 = __float2bfloat16(v1);
                __nv_bfloat162 hh; hh.x = h0; hh.y = h1;
                __nv_bfloat162 ll;
                ll.x = __float2bfloat16(v0 - __bfloat162float(h0));
                ll.y = __float2bfloat16(v1 - __bfloat162float(h1));
                *(__nv_bfloat162*)(Chi + base) = hh;
                *(__nv_bfloat162*)(Clo + base) = ll;
            }
        }
    }
}

struct QkvsPtrs {
    const __nv_bfloat16 *bh[4], *bl[4];
    float* c[4];
};

__global__ __launch_bounds__(512, 1) void qkvs_gemm(
    const __nv_bfloat16* __restrict__ Ahi, const __nv_bfloat16* __restrict__ Alo,
    QkvsPtrs pp, int M)
{
    extern __shared__ char smem[];
    __nv_bfloat16* sAh = (__nv_bfloat16*)(smem + OFF_AH);
    __nv_bfloat16* sAl = (__nv_bfloat16*)(smem + OFF_AL);
    __nv_bfloat16* sBh = (__nv_bfloat16*)(smem + OFF_BH);
    __nv_bfloat16* sBl = (__nv_bfloat16*)(smem + OFF_BL);
    int tid = threadIdx.x;
    int m0 = blockIdx.x * 128;
    int sel = blockIdx.y;

    gemm_stage_A(Ahi, Alo, sAh, sAl, m0, M, tid);
    gemm_stage_B(pp.bh[sel], pp.bl[sel], sBh, sBl, HID, tid);
    __syncthreads();

    int lane = tid & 31, wid = tid >> 5;
    int grp = lane >> 2, qd = lane & 3;
    int mt = (wid >> 1) * 16;
    int ntBeg = (wid & 1) * 8;

    float acc[8][4];
    #pragma unroll
    for (int i = 0; i < 8; i++)
        #pragma unroll
        for (int j = 0; j < 4; j++) acc[i][j] = 0.f;

    gemm_mainloop(sAh, sAl, sBh, sBl, acc, mt, lane, ntBeg, 8);

    float* C = pp.c[sel];
    #pragma unroll
    for (int t = 0; t < 8; t++) {
        int col = (ntBeg + t) * 8 + 2 * qd;
        #pragma unroll
        for (int half = 0; half < 2; half++) {
            int row = m0 + mt + grp + half * 8;
            if (row >= M) continue;
            size_t base = (size_t)row * HID + col;
            *(float2*)(C + base) = make_float2(acc[t][half * 2], acc[t][half * 2 + 1]);
        }
    }
}

// ======================= edge attention =====================================
__global__ __launch_bounds__(128) void attn_kernel(
    const float* __restrict__ q, const float* __restrict__ k,
    const float* __restrict__ v, const float* __restrict__ skip,
    const float* __restrict__ We, float* __restrict__ out,
    __nv_bfloat16* __restrict__ outhi, __nv_bfloat16* __restrict__ outlo)
{
    __shared__ float we_s[HID * 3];
    int tid = threadIdx.x;
    for (int i = tid; i < HID * 3; i += blockDim.x) we_s[i] = We[i];
    __syncthreads();

    int warp = blockIdx.x * (blockDim.x >> 5) + (tid >> 5);
    if (warp >= N_NODES) return;
    int lane = tid & 31;
    int col  = (lane >> 3) * DH + (lane & 7) * 4;

    float wr[12];
    #pragma unroll
    for (int i = 0; i < 4; i++)
        #pragma unroll
        for (int c = 0; c < 3; c++)
            wr[i * 3 + c] = we_s[3 * (col + i) + c];

    float4 qv = *(const float4*)(q + (size_t)warp * HID + col);
    float m = -INFINITY, ssum = 0.f;
    float ox = 0.f, oy = 0.f, oz = 0.f, ow = 0.f;

    int e0 = g_off[warp], e1 = g_off[warp + 1];
    for (int e = e0; e < e1; e++) {
        int src = g_ssrc[e];
        float a0 = g_sattr[3 * e + 0];
        float a1 = g_sattr[3 * e + 1];
        float a2 = g_sattr[3 * e + 2];
        float4 kv = *(const float4*)(k + (size_t)src * HID + col);
        float4 vv = *(const float4*)(v + (size_t)src * HID + col);
        float ec0 = fmaf(a0, wr[0], fmaf(a1, wr[1],  a2 * wr[2]));
        float ec1 = fmaf(a0, wr[3], fmaf(a1, wr[4],  a2 * wr[5]));
        float ec2 = fmaf(a0, wr[6], fmaf(a1, wr[7],  a2 * wr[8]));
        float ec3 = fmaf(a0, wr[9], fmaf(a1, wr[10], a2 * wr[11]));
        float kx = kv.x + ec0, ky = kv.y + ec1, kz = kv.z + ec2, kw = kv.w + ec3;
        float dot = qv.x * kx + qv.y * ky + qv.z * kz + qv.w * kw;
        dot += __shfl_xor_sync(0xffffffffu, dot, 1);
        dot += __shfl_xor_sync(0xffffffffu, dot, 2);
        dot += __shfl_xor_sync(0xffffffffu, dot, 4);
        float alpha = dot * 0.17677669529663687f;
        float nm = fmaxf(m, alpha);
        float sc = __expf(m - nm);
        float p  = __expf(alpha - nm);
        ssum = ssum * sc + p;
        ox = ox * sc + p * (vv.x + ec0);
        oy = oy * sc + p * (vv.y + ec1);
        oz = oz * sc + p * (vv.z + ec2);
        ow = ow * sc + p * (vv.w + ec3);
        m = nm;
    }
    float inv = 1.0f / fmaxf(ssum, 1e-16f);
    float4 sk = *(const float4*)(skip + (size_t)warp * HID + col);
    float o0 = ox * inv + sk.x, o1 = oy * inv + sk.y;
    float o2 = oz * inv + sk.z, o3 = ow * inv + sk.w;
    size_t base = (size_t)warp * HID + col;
    *(float4*)(out + base) = make_float4(o0, o1, o2, o3);

    float vs[4] = {o0, o1, o2, o3};
    #pragma unroll
    for (int pr = 0; pr < 2; pr++) {
        float v0 = vs[pr * 2], v1 = vs[pr * 2 + 1];
        __nv_bfloat16 h0 = __float2bfloat16(v0);
        __nv_bfloat16 h1 = __float2bfloat16(v1);
        __nv_bfloat162 hh; hh.x = h0; hh.y = h1;
        __nv_bfloat162 ll;
        ll.x = __float2bfloat16(v0 - __bfloat162float(h0));
        ll.y = __float2bfloat16(v1 - __bfloat162float(h1));
        *(__nv_bfloat162*)(outhi + base + pr * 2) = hh;
        *(__nv_bfloat162*)(outlo + base + pr * 2) = ll;
    }
}

// ======================= launch =============================================
static inline void run_mm(cudaStream_t s,
                          const __nv_bfloat16* Ahi, const __nv_bfloat16* Alo,
                          const __nv_bfloat16* Bhi, const __nv_bfloat16* Blo,
                          const float* bias, const float* res,
                          float* C, __nv_bfloat16* Chi, __nv_bfloat16* Clo,
                          int M, int Nout, int act) {
    int grid = (M + 127) / 128;
    mma_gemm<<<grid, 512, MMA_SMEM, s>>>(Ahi, Alo, Bhi, Blo, bias, res, C, Chi, Clo, M, Nout, act);
}

extern "C" void kernel_launch(void* const* d_in, const int* in_sizes, int n_in,
                              void* d_out, int out_size) {
    const float* x    = (const float*)d_in[0];
    const int*   ei   = (const int*)  d_in[1];
    const float* attr = (const float*)d_in[2];
    const float* Wq1 = (const float*)d_in[3],  *Wk1 = (const float*)d_in[4];
    const float* Wv1 = (const float*)d_in[5],  *We1 = (const float*)d_in[6];
    const float* Ws1 = (const float*)d_in[7];
    const float* M1a = (const float*)d_in[8],  *b1a = (const float*)d_in[9];
    const float* M1b = (const float*)d_in[10], *b1b = (const float*)d_in[11];
    const float* Wq2 = (const float*)d_in[12], *Wk2 = (const float*)d_in[13];
    const float* Wv2 = (const float*)d_in[14], *We2 = (const float*)d_in[15];
    const float* Ws2 = (const float*)d_in[16];
    const float* M2a = (const float*)d_in[17], *b2a = (const float*)d_in[18];
    const float* M2b = (const float*)d_in[19], *b2b = (const float*)d_in[20];
    const float* Wf1 = (const float*)d_in[21], *bf1 = (const float*)d_in[22];
    const float* Wf2 = (const float*)d_in[23], *bf2 = (const float*)d_in[24];
    float* out = (float*)d_out;

    float *q, *k, *v, *sk, *h, *t1, *t2;
    cudaGetSymbolAddress((void**)&q,  g_q);
    cudaGetSymbolAddress((void**)&k,  g_k);
    cudaGetSymbolAddress((void**)&v,  g_v);
    cudaGetSymbolAddress((void**)&sk, g_sk);
    cudaGetSymbolAddress((void**)&h,  g_h);
    cudaGetSymbolAddress((void**)&t1, g_t1);
    cudaGetSymbolAddress((void**)&t2, g_t2);

    __nv_bfloat16 *xhi, *xlo, *hhi, *hlo, *t1hi, *t1lo, *t2hi, *t2lo, *whi, *wlo;
    cudaGetSymbolAddress((void**)&xhi,  g_xhi);
    cudaGetSymbolAddress((void**)&xlo,  g_xlo);
    cudaGetSymbolAddress((void**)&hhi,  g_hhi);
    cudaGetSymbolAddress((void**)&hlo,  g_hlo);
    cudaGetSymbolAddress((void**)&t1hi, g_t1hi);
    cudaGetSymbolAddress((void**)&t1lo, g_t1lo);
    cudaGetSymbolAddress((void**)&t2hi, g_t2hi);
    cudaGetSymbolAddress((void**)&t2lo, g_t2lo);
    cudaGetSymbolAddress((void**)&whi,  g_whi);
    cudaGetSymbolAddress((void**)&wlo,  g_wlo);

    cudaFuncSetAttribute(mma_gemm,  cudaFuncAttributeMaxDynamicSharedMemorySize, MMA_SMEM);
    cudaFuncSetAttribute(qkvs_gemm, cudaFuncAttributeMaxDynamicSharedMemorySize, MMA_SMEM);

    cudaStream_t s = 0;
    #define WHI(i) (whi + (i) * 16384)
    #define WLO(i) (wlo + (i) * 16384)

    int gblocks = (N_NODES + 127) / 128;
    int ablocks = (N_NODES * 32 + 127) / 128;

    // 1: all splits + deg zero
    WPtrs wp;
    const float* wsrc[14] = {Wq1, Wk1, Wv1, Ws1, M1a, M1b, Wq2, Wk2, Wv2, Ws2, M2a, M2b, Wf1, Wf2};
    for (int i = 0; i < 14; i++) wp.p[i] = wsrc[i];
    bigsplit_kernel<<<WSPLIT_BLOCKS + ZERO_BLOCKS + XSPLIT_BLOCKS, 256, 0, s>>>(wp, x);
    // 2: hist
    hist_kernel<<<(N_EDGES + 255) / 256, 256, 0, s>>>(ei);
    // 3: scan stage 1
    scan_s1<<<SCAN_NBLK, 1024, 0, s>>>();
    // 4: layer-1 fused QKVS GEMM  (ncu capture slot)
    QkvsPtrs p1;
    for (int i = 0; i < 4; i++) { p1.bh[i] = WHI(i); p1.bl[i] = WLO(i); }
    p1.c[0] = q; p1.c[1] = k; p1.c[2] = v; p1.c[3] = sk;
    qkvs_gemm<<<dim3(gblocks, 4), 512, MMA_SMEM, s>>>(xhi, xlo, p1, N_NODES);
    // 5-6: scan stages 2,3
    scan_s2<<<1, 64, 0, s>>>();
    scan_s3<<<(N_NODES + 255) / 256, 256, 0, s>>>();
    // 7: scatter
    scatter_kernel<<<(N_EDGES + 255) / 256, 256, 0, s>>>(ei, attr);

    // layer 1
    attn_kernel<<<ablocks, 128, 0, s>>>(q, k, v, sk, We1, h, hhi, hlo);
    run_mm(s, hhi,  hlo,  WHI(4), WLO(4), b1a, nullptr, t1, t1hi, t1lo, N_NODES, HID, 1);
    run_mm(s, t1hi, t1lo, WHI(5), WLO(5), b1b, h,       t2, t2hi, t2lo, N_NODES, HID, 1);

    // layer 2
    QkvsPtrs p2;
    for (int i = 0; i < 4; i++) { p2.bh[i] = WHI(6 + i); p2.bl[i] = WLO(6 + i); }
    p2.c[0] = q; p2.c[1] = k; p2.c[2] = v; p2.c[3] = sk;
    qkvs_gemm<<<dim3(gblocks, 4), 512, MMA_SMEM, s>>>(t2hi, t2lo, p2, N_NODES);
    attn_kernel<<<ablocks, 128, 0, s>>>(q, k, v, sk, We2, h, hhi, hlo);
    run_mm(s, hhi,  hlo,  WHI(10), WLO(10), b2a, nullptr, t1, t1hi, t1lo, N_NODES, HID, 1);
    run_mm(s, t1hi, t1lo, WHI(11), WLO(11), b2b, h,       t2, t2hi, t2lo, N_NODES, HID, 1);

    // final MLP
    run_mm(s, t2hi, t2lo, WHI(12), WLO(12), bf1, nullptr, t1, t1hi, t1lo, N_NODES, HID, 1);
    run_mm(s, t1hi, t1lo, WHI(13), WLO(13), bf2, nullptr, out, nullptr, nullptr, N_NODES, OUTD, 1);
}

// round 9
// speedup vs baseline: 1.2058x; 1.0252x over previous
#include <cuda_runtime.h>
#include <cuda_bf16.h>
#include <math.h>
#include <stdint.h>

#define N_NODES 50000
#define N_EDGES 800000
#define HID     128
#define NHEAD   4
#define DH      32
#define OUTD    64

// ======================= scratch (device globals) ===========================
__device__ float g_q [N_NODES * HID];
__device__ float g_k [N_NODES * HID];
__device__ float g_v [N_NODES * HID];
__device__ float g_sk[N_NODES * HID];
__device__ float g_h [N_NODES * HID];
__device__ float g_t1[N_NODES * HID];
__device__ float g_t2[N_NODES * HID];
__device__ int   g_deg [N_NODES];
__device__ int   g_off [N_NODES + 1];
__device__ int   g_cur [N_NODES];
__device__ int   g_ssrc[N_EDGES];
__device__ float g_sattr[N_EDGES * 3];

#define SCAN_NBLK 49
__device__ int g_bsum[SCAN_NBLK];
__device__ int g_bpre[SCAN_NBLK];

__device__ __nv_bfloat16 g_xhi [N_NODES * HID];
__device__ __nv_bfloat16 g_xlo [N_NODES * HID];
__device__ __nv_bfloat16 g_hhi [N_NODES * HID];
__device__ __nv_bfloat16 g_hlo [N_NODES * HID];
__device__ __nv_bfloat16 g_t1hi[N_NODES * HID];
__device__ __nv_bfloat16 g_t1lo[N_NODES * HID];
__device__ __nv_bfloat16 g_t2hi[N_NODES * HID];
__device__ __nv_bfloat16 g_t2lo[N_NODES * HID];
__device__ __nv_bfloat16 g_whi[14 * 16384];
__device__ __nv_bfloat16 g_wlo[14 * 16384];

// ============ fused: weight split + deg zero + x split (one launch) =========
struct WPtrs { const float* p[14]; };

#define WSPLIT_BLOCKS 864
#define ZERO_BLOCKS   196
#define XSPLIT_BLOCKS 25000

__global__ void bigsplit_kernel(WPtrs wp, const float* __restrict__ x) {
    int b = blockIdx.x;
    if (b < WSPLIT_BLOCKS) {
        int mi, cb;
        if (b < 832) { mi = b >> 6; cb = b & 63; }
        else         { mi = 13;     cb = b - 832; }
        int i = cb * 256 + threadIdx.x;
        int n = (mi == 13) ? 8192 : 16384;
        if (i < n) {
            float v = wp.p[mi][i];
            __nv_bfloat16 h = __float2bfloat16(v);
            g_whi[mi * 16384 + i] = h;
            g_wlo[mi * 16384 + i] = __float2bfloat16(v - __bfloat162float(h));
        }
    } else if (b < WSPLIT_BLOCKS + ZERO_BLOCKS) {
        int i = (b - WSPLIT_BLOCKS) * 256 + threadIdx.x;
        if (i < N_NODES) g_deg[i] = 0;
    } else {
        int i = (b - WSPLIT_BLOCKS - ZERO_BLOCKS) * 256 + threadIdx.x;
        float v = x[i];
        __nv_bfloat16 h = __float2bfloat16(v);
        g_xhi[i] = h;
        g_xlo[i] = __float2bfloat16(v - __bfloat162float(h));
    }
}

// ======================= edge sorting =======================================
__global__ void hist_kernel(const int* __restrict__ ei) {
    int e = blockIdx.x * blockDim.x + threadIdx.x;
    if (e < N_EDGES) atomicAdd(&g_deg[ei[N_EDGES + e]], 1);
}

__global__ __launch_bounds__(1024) void scan_s1() {
    __shared__ int wsum[32];
    int tid = threadIdx.x, lane = tid & 31, wid = tid >> 5;
    int i = blockIdx.x * 1024 + tid;
    int v = (i < N_NODES) ? g_deg[i] : 0;
    int x = v;
    #pragma unroll
    for (int d = 1; d < 32; d <<= 1) {
        int y = __shfl_up_sync(0xffffffffu, x, d);
        if (lane >= d) x += y;
    }
    if (lane == 31) wsum[wid] = x;
    __syncthreads();
    if (wid == 0) {
        int s = wsum[lane];
        #pragma unroll
        for (int d = 1; d < 32; d <<= 1) {
            int y = __shfl_up_sync(0xffffffffu, s, d);
            if (lane >= d) s += y;
        }
        wsum[lane] = s;
    }
    __syncthreads();
    int incl = x + (wid > 0 ? wsum[wid - 1] : 0);
    if (i < N_NODES) g_off[i] = incl - v;
    if (tid == 1023) g_bsum[blockIdx.x] = incl;
}

__global__ void scan_s2() {
    __shared__ int w0sum;
    int tid = threadIdx.x;
    int lane = tid & 31, wid = tid >> 5;
    int v = (tid < SCAN_NBLK) ? g_bsum[tid] : 0;
    int x = v;
    #pragma unroll
    for (int d = 1; d < 32; d <<= 1) {
        int y = __shfl_up_sync(0xffffffffu, x, d);
        if (lane >= d) x += y;
    }
    if (wid == 0 && lane == 31) w0sum = x;
    __syncthreads();
    int incl = x + (wid ? w0sum : 0);
    if (tid < SCAN_NBLK) g_bpre[tid] = incl - v;
    if (tid == SCAN_NBLK - 1) g_off[N_NODES] = incl;
}

__global__ void scan_s3() {
    int i = blockIdx.x * blockDim.x + threadIdx.x;
    if (i < N_NODES) {
        int o = g_off[i] + g_bpre[i >> 10];
        g_off[i] = o;
        g_cur[i] = o;
    }
}

__global__ void scatter_kernel(const int* __restrict__ ei, const float* __restrict__ attr) {
    int e = blockIdx.x * blockDim.x + threadIdx.x;
    if (e < N_EDGES) {
        int dst = ei[N_EDGES + e];
        int pos = atomicAdd(&g_cur[dst], 1);
        g_ssrc[pos] = ei[e];
        g_sattr[3 * pos + 0] = attr[3 * e + 0];
        g_sattr[3 * pos + 1] = attr[3 * e + 1];
        g_sattr[3 * pos + 2] = attr[3 * e + 2];
    }
}

// ======================= GELU ==============================================
__device__ __forceinline__ float gelu_f(float x) {
    float x3 = x * x * x;
    float u = 0.7978845608028654f * (x + 0.044715f * x3);
    return 0.5f * x * (1.0f + tanhf(u));
}

// ======================= HMMA GEMM: K-split, 2 CTAs/SM ======================
// K staged in two 64-wide slabs. smem/CTA = 4 arrays x 128rows x 72 bf16 = 72KB.
#define SROW2 72
#define SLAB_BYTES 18432
#define OFF2_AH 0
#define OFF2_AL 18432
#define OFF2_BH 36864
#define OFF2_BL 55296
#define MMA_SMEM2 73728

__device__ __forceinline__ void mma16816(float* c,
    uint32_t a0, uint32_t a1, uint32_t a2, uint32_t a3,
    uint32_t b0, uint32_t b1) {
    asm volatile(
        "mma.sync.aligned.m16n8k16.row.col.f32.bf16.bf16.f32 "
        "{%0,%1,%2,%3}, {%4,%5,%6,%7}, {%8,%9}, {%0,%1,%2,%3};"
        : "+f"(c[0]), "+f"(c[1]), "+f"(c[2]), "+f"(c[3])
        : "r"(a0), "r"(a1), "r"(a2), "r"(a3), "r"(b0), "r"(b1));
}

__device__ __forceinline__ void ldsm_x4(uint32_t& r0, uint32_t& r1,
                                        uint32_t& r2, uint32_t& r3, uint32_t addr) {
    asm volatile("ldmatrix.sync.aligned.m8n8.x4.shared.b16 {%0,%1,%2,%3}, [%4];"
                 : "=r"(r0), "=r"(r1), "=r"(r2), "=r"(r3) : "r"(addr));
}

__device__ __forceinline__ uint32_t smem_u32(const void* p) {
    return (uint32_t)__cvta_generic_to_shared(p);
}

// stage one K=64 slab of A (128 rows): 256 threads, 2/row, 4 uint4 each
__device__ __forceinline__ void stage_slab_A(
    const __nv_bfloat16* Ahi, const __nv_bfloat16* Alo,
    __nv_bfloat16* sAh, __nv_bfloat16* sAl, int m0, int M, int slab, int tid)
{
    int row = tid >> 1;
    int u0  = (tid & 1) * 4;
    int gr  = m0 + row;
    bool ok = gr < M;
    const uint4* ah = (const uint4*)(Ahi + (size_t)gr * 128 + slab * 64);
    const uint4* al = (const uint4*)(Alo + (size_t)gr * 128 + slab * 64);
    uint4 z = make_uint4(0u, 0u, 0u, 0u);
    #pragma unroll
    for (int u = u0; u < u0 + 4; u++) {
        *(uint4*)(&sAh[row * SROW2 + u * 8]) = ok ? ah[u] : z;
        *(uint4*)(&sAl[row * SROW2 + u * 8]) = ok ? al[u] : z;
    }
}

__device__ __forceinline__ void stage_slab_B(
    const __nv_bfloat16* Bhi, const __nv_bfloat16* Blo,
    __nv_bfloat16* sBh, __nv_bfloat16* sBl, int Nout, int slab, int tid)
{
    int row = tid >> 1;
    if (row < Nout) {
        int u0 = (tid & 1) * 4;
        const uint4* bh = (const uint4*)(Bhi + (size_t)row * 128 + slab * 64);
        const uint4* bl = (const uint4*)(Blo + (size_t)row * 128 + slab * 64);
        #pragma unroll
        for (int u = u0; u < u0 + 4; u++) {
            *(uint4*)(&sBh[row * SROW2 + u * 8]) = bh[u];
            *(uint4*)(&sBl[row * SROW2 + u * 8]) = bl[u];
        }
    }
}

// one K=64 slab of mainloop; warp tile 32 x (8*ntN), ntN even
__device__ __forceinline__ void mainloop_slab(
    const __nv_bfloat16* sAh, const __nv_bfloat16* sAl,
    const __nv_bfloat16* sBh, const __nv_bfloat16* sBl,
    float acc[2][8][4], int mt, int lane, int ntBeg, int ntN)
{
    uint32_t aAh = smem_u32(sAh), aAl = smem_u32(sAl);
    uint32_t aBh = smem_u32(sBh), aBl = smem_u32(sBl);
    int arow = lane & 15, akh = 8 * (lane >> 4);
    int brow = lane & 7;
    int bsel = lane >> 4;
    int bk   = 8 * ((lane >> 3) & 1);

    for (int kt = 0; kt < 64; kt += 16) {
        uint32_t ah[2][4], al[2][4];
        #pragma unroll
        for (int mi = 0; mi < 2; mi++) {
            int aoff = (mt + mi * 16 + arow) * SROW2 + akh + kt;
            ldsm_x4(ah[mi][0], ah[mi][1], ah[mi][2], ah[mi][3], aAh + (uint32_t)aoff * 2);
            ldsm_x4(al[mi][0], al[mi][1], al[mi][2], al[mi][3], aAl + (uint32_t)aoff * 2);
        }
        #pragma unroll
        for (int p = 0; p < 4; p++) {
            if (2 * p >= ntN) break;
            int nt = ntBeg + 2 * p + bsel;
            int boff = (nt * 8 + brow) * SROW2 + bk + kt;
            uint32_t bh0, bh1, bh2, bh3, bl0, bl1, bl2, bl3;
            ldsm_x4(bh0, bh1, bh2, bh3, aBh + (uint32_t)boff * 2);
            ldsm_x4(bl0, bl1, bl2, bl3, aBl + (uint32_t)boff * 2);
            #pragma unroll
            for (int mi = 0; mi < 2; mi++) {
                mma16816(acc[mi][2 * p + 0], ah[mi][0], ah[mi][1], ah[mi][2], ah[mi][3], bh0, bh1);
                mma16816(acc[mi][2 * p + 0], ah[mi][0], ah[mi][1], ah[mi][2], ah[mi][3], bl0, bl1);
                mma16816(acc[mi][2 * p + 0], al[mi][0], al[mi][1], al[mi][2], al[mi][3], bh0, bh1);
                mma16816(acc[mi][2 * p + 1], ah[mi][0], ah[mi][1], ah[mi][2], ah[mi][3], bh2, bh3);
                mma16816(acc[mi][2 * p + 1], ah[mi][0], ah[mi][1], ah[mi][2], ah[mi][3], bl2, bl3);
                mma16816(acc[mi][2 * p + 1], al[mi][0], al[mi][1], al[mi][2], al[mi][3], bh2, bh3);
            }
        }
    }
}

__global__ __launch_bounds__(256, 2) void mma_gemm(
    const __nv_bfloat16* __restrict__ Ahi, const __nv_bfloat16* __restrict__ Alo,
    const __nv_bfloat16* __restrict__ Bhi, const __nv_bfloat16* __restrict__ Blo,
    const float* __restrict__ bias, const float* __restrict__ res,
    float* __restrict__ C, __nv_bfloat16* __restrict__ Chi, __nv_bfloat16* __restrict__ Clo,
    int M, int Nout, int act)
{
    extern __shared__ char smem[];
    __nv_bfloat16* sAh = (__nv_bfloat16*)(smem + OFF2_AH);
    __nv_bfloat16* sAl = (__nv_bfloat16*)(smem + OFF2_AL);
    __nv_bfloat16* sBh = (__nv_bfloat16*)(smem + OFF2_BH);
    __nv_bfloat16* sBl = (__nv_bfloat16*)(smem + OFF2_BL);
    int tid = threadIdx.x;
    int m0 = blockIdx.x * 128;

    int lane = tid & 31, wid = tid >> 5;
    int grp = lane >> 2, qd = lane & 3;
    int mt = (wid >> 1) * 32;
    int NT = Nout >> 3;
    int ntBeg = (wid & 1) * (NT >> 1);
    int ntN   = NT >> 1;                 // 8 (Nout=128) or 4 (Nout=64)

    float acc[2][8][4];
    #pragma unroll
    for (int mi = 0; mi < 2; mi++)
        #pragma unroll
        for (int i = 0; i < 8; i++)
            #pragma unroll
            for (int j = 0; j < 4; j++) acc[mi][i][j] = 0.f;

    #pragma unroll
    for (int s = 0; s < 2; s++) {
        if (s) __syncthreads();
        stage_slab_A(Ahi, Alo, sAh, sAl, m0, M, s, tid);
        stage_slab_B(Bhi, Blo, sBh, sBl, Nout, s, tid);
        __syncthreads();
        mainloop_slab(sAh, sAl, sBh, sBl, acc, mt, lane, ntBeg, ntN);
    }

    #pragma unroll
    for (int mi = 0; mi < 2; mi++) {
        #pragma unroll
        for (int t = 0; t < 8; t++) {
            if (t >= ntN) break;
            int col = (ntBeg + t) * 8 + 2 * qd;
            float bsum0 = bias ? bias[col]     : 0.f;
            float bsum1 = bias ? bias[col + 1] : 0.f;
            #pragma unroll
            for (int half = 0; half < 2; half++) {
                int row = m0 + mt + mi * 16 + grp + half * 8;
                if (row >= M) continue;
                float v0 = acc[mi][t][half * 2 + 0] + bsum0;
                float v1 = acc[mi][t][half * 2 + 1] + bsum1;
                if (act) { v0 = gelu_f(v0); v1 = gelu_f(v1); }
                size_t base = (size_t)row * Nout + col;
                if (res) { v0 += res[base]; v1 += res[base + 1]; }
                *(float2*)(C + base) = make_float2(v0, v1);
                if (Chi) {
                    __nv_bfloat16 h0 = __float2bfloat16(v0);
                    __nv_bfloat16 h1 = __float2bfloat16(v1);
                    __nv_bfloat162 hh; hh.x = h0; hh.y = h1;
                    __nv_bfloat162 ll;
                    ll.x = __float2bfloat16(v0 - __bfloat162float(h0));
                    ll.y = __float2bfloat16(v1 - __bfloat162float(h1));
                    *(__nv_bfloat162*)(Chi + base) = hh;
                    *(__nv_bfloat162*)(Clo + base) = ll;
                }
            }
        }
    }
}

struct QkvsPtrs {
    const __nv_bfloat16 *bh[4], *bl[4];
    float* c[4];
};

__global__ __launch_bounds__(256, 2) void qkvs_gemm(
    const __nv_bfloat16* __restrict__ Ahi, const __nv_bfloat16* __restrict__ Alo,
    QkvsPtrs pp, int M)
{
    extern __shared__ char smem[];
    __nv_bfloat16* sAh = (__nv_bfloat16*)(smem + OFF2_AH);
    __nv_bfloat16* sAl = (__nv_bfloat16*)(smem + OFF2_AL);
    __nv_bfloat16* sBh = (__nv_bfloat16*)(smem + OFF2_BH);
    __nv_bfloat16* sBl = (__nv_bfloat16*)(smem + OFF2_BL);
    int tid = threadIdx.x;
    int m0 = blockIdx.x * 128;
    int sel = blockIdx.y;

    int lane = tid & 31, wid = tid >> 5;
    int grp = lane >> 2, qd = lane & 3;
    int mt = (wid >> 1) * 32;
    int ntBeg = (wid & 1) * 8;

    float acc[2][8][4];
    #pragma unroll
    for (int mi = 0; mi < 2; mi++)
        #pragma unroll
        for (int i = 0; i < 8; i++)
            #pragma unroll
            for (int j = 0; j < 4; j++) acc[mi][i][j] = 0.f;

    #pragma unroll
    for (int s = 0; s < 2; s++) {
        if (s) __syncthreads();
        stage_slab_A(Ahi, Alo, sAh, sAl, m0, M, s, tid);
        stage_slab_B(pp.bh[sel], pp.bl[sel], sBh, sBl, HID, s, tid);
        __syncthreads();
        mainloop_slab(sAh, sAl, sBh, sBl, acc, mt, lane, ntBeg, 8);
    }

    float* C = pp.c[sel];
    #pragma unroll
    for (int mi = 0; mi < 2; mi++) {
        #pragma unroll
        for (int t = 0; t < 8; t++) {
            int col = (ntBeg + t) * 8 + 2 * qd;
            #pragma unroll
            for (int half = 0; half < 2; half++) {
                int row = m0 + mt + mi * 16 + grp + half * 8;
                if (row >= M) continue;
                size_t base = (size_t)row * HID + col;
                *(float2*)(C + base) = make_float2(acc[mi][t][half * 2], acc[mi][t][half * 2 + 1]);
            }
        }
    }
}

// ======================= edge attention =====================================
__global__ __launch_bounds__(128) void attn_kernel(
    const float* __restrict__ q, const float* __restrict__ k,
    const float* __restrict__ v, const float* __restrict__ skip,
    const float* __restrict__ We, float* __restrict__ out,
    __nv_bfloat16* __restrict__ outhi, __nv_bfloat16* __restrict__ outlo)
{
    __shared__ float we_s[HID * 3];
    int tid = threadIdx.x;
    for (int i = tid; i < HID * 3; i += blockDim.x) we_s[i] = We[i];
    __syncthreads();

    int warp = blockIdx.x * (blockDim.x >> 5) + (tid >> 5);
    if (warp >= N_NODES) return;
    int lane = tid & 31;
    int col  = (lane >> 3) * DH + (lane & 7) * 4;

    float wr[12];
    #pragma unroll
    for (int i = 0; i < 4; i++)
        #pragma unroll
        for (int c = 0; c < 3; c++)
            wr[i * 3 + c] = we_s[3 * (col + i) + c];

    float4 qv = *(const float4*)(q + (size_t)warp * HID + col);
    float m = -INFINITY, ssum = 0.f;
    float ox = 0.f, oy = 0.f, oz = 0.f, ow = 0.f;

    int e0 = g_off[warp], e1 = g_off[warp + 1];
    for (int e = e0; e < e1; e++) {
        int src = g_ssrc[e];
        float a0 = g_sattr[3 * e + 0];
        float a1 = g_sattr[3 * e + 1];
        float a2 = g_sattr[3 * e + 2];
        float4 kv = *(const float4*)(k + (size_t)src * HID + col);
        float4 vv = *(const float4*)(v + (size_t)src * HID + col);
        float ec0 = fmaf(a0, wr[0], fmaf(a1, wr[1],  a2 * wr[2]));
        float ec1 = fmaf(a0, wr[3], fmaf(a1, wr[4],  a2 * wr[5]));
        float ec2 = fmaf(a0, wr[6], fmaf(a1, wr[7],  a2 * wr[8]));
        float ec3 = fmaf(a0, wr[9], fmaf(a1, wr[10], a2 * wr[11]));
        float kx = kv.x + ec0, ky = kv.y + ec1, kz = kv.z + ec2, kw = kv.w + ec3;
        float dot = qv.x * kx + qv.y * ky + qv.z * kz + qv.w * kw;
        dot += __shfl_xor_sync(0xffffffffu, dot, 1);
        dot += __shfl_xor_sync(0xffffffffu, dot, 2);
        dot += __shfl_xor_sync(0xffffffffu, dot, 4);
        float alpha = dot * 0.17677669529663687f;
        float nm = fmaxf(m, alpha);
        float sc = __expf(m - nm);
        float p  = __expf(alpha - nm);
        ssum = ssum * sc + p;
        ox = ox * sc + p * (vv.x + ec0);
        oy = oy * sc + p * (vv.y + ec1);
        oz = oz * sc + p * (vv.z + ec2);
        ow = ow * sc + p * (vv.w + ec3);
        m = nm;
    }
    float inv = 1.0f / fmaxf(ssum, 1e-16f);
    float4 sk = *(const float4*)(skip + (size_t)warp * HID + col);
    float o0 = ox * inv + sk.x, o1 = oy * inv + sk.y;
    float o2 = oz * inv + sk.z, o3 = ow * inv + sk.w;
    size_t base = (size_t)warp * HID + col;
    *(float4*)(out + base) = make_float4(o0, o1, o2, o3);

    float vs[4] = {o0, o1, o2, o3};
    #pragma unroll
    for (int pr = 0; pr < 2; pr++) {
        float v0 = vs[pr * 2], v1 = vs[pr * 2 + 1];
        __nv_bfloat16 h0 = __float2bfloat16(v0);
        __nv_bfloat16 h1 = __float2bfloat16(v1);
        __nv_bfloat162 hh; hh.x = h0; hh.y = h1;
        __nv_bfloat162 ll;
        ll.x = __float2bfloat16(v0 - __bfloat162float(h0));
        ll.y = __float2bfloat16(v1 - __bfloat162float(h1));
        *(__nv_bfloat162*)(outhi + base + pr * 2) = hh;
        *(__nv_bfloat162*)(outlo + base + pr * 2) = ll;
    }
}

// ======================= launch =============================================
static inline void run_mm(cudaStream_t s,
                          const __nv_bfloat16* Ahi, const __nv_bfloat16* Alo,
                          const __nv_bfloat16* Bhi, const __nv_bfloat16* Blo,
                          const float* bias, const float* res,
                          float* C, __nv_bfloat16* Chi, __nv_bfloat16* Clo,
                          int M, int Nout, int act) {
    int grid = (M + 127) / 128;
    mma_gemm<<<grid, 256, MMA_SMEM2, s>>>(Ahi, Alo, Bhi, Blo, bias, res, C, Chi, Clo, M, Nout, act);
}

extern "C" void kernel_launch(void* const* d_in, const int* in_sizes, int n_in,
                              void* d_out, int out_size) {
    const float* x    = (const float*)d_in[0];
    const int*   ei   = (const int*)  d_in[1];
    const float* attr = (const float*)d_in[2];
    const float* Wq1 = (const float*)d_in[3],  *Wk1 = (const float*)d_in[4];
    const float* Wv1 = (const float*)d_in[5],  *We1 = (const float*)d_in[6];
    const float* Ws1 = (const float*)d_in[7];
    const float* M1a = (const float*)d_in[8],  *b1a = (const float*)d_in[9];
    const float* M1b = (const float*)d_in[10], *b1b = (const float*)d_in[11];
    const float* Wq2 = (const float*)d_in[12], *Wk2 = (const float*)d_in[13];
    const float* Wv2 = (const float*)d_in[14], *We2 = (const float*)d_in[15];
    const float* Ws2 = (const float*)d_in[16];
    const float* M2a = (const float*)d_in[17], *b2a = (const float*)d_in[18];
    const float* M2b = (const float*)d_in[19], *b2b = (const float*)d_in[20];
    const float* Wf1 = (const float*)d_in[21], *bf1 = (const float*)d_in[22];
    const float* Wf2 = (const float*)d_in[23], *bf2 = (const float*)d_in[24];
    float* out = (float*)d_out;

    float *q, *k, *v, *sk, *h, *t1, *t2;
    cudaGetSymbolAddress((void**)&q,  g_q);
    cudaGetSymbolAddress((void**)&k,  g_k);
    cudaGetSymbolAddress((void**)&v,  g_v);
    cudaGetSymbolAddress((void**)&sk, g_sk);
    cudaGetSymbolAddress((void**)&h,  g_h);
    cudaGetSymbolAddress((void**)&t1, g_t1);
    cudaGetSymbolAddress((void**)&t2, g_t2);

    __nv_bfloat16 *xhi, *xlo, *hhi, *hlo, *t1hi, *t1lo, *t2hi, *t2lo, *whi, *wlo;
    cudaGetSymbolAddress((void**)&xhi,  g_xhi);
    cudaGetSymbolAddress((void**)&xlo,  g_xlo);
    cudaGetSymbolAddress((void**)&hhi,  g_hhi);
    cudaGetSymbolAddress((void**)&hlo,  g_hlo);
    cudaGetSymbolAddress((void**)&t1hi, g_t1hi);
    cudaGetSymbolAddress((void**)&t1lo, g_t1lo);
    cudaGetSymbolAddress((void**)&t2hi, g_t2hi);
    cudaGetSymbolAddress((void**)&t2lo, g_t2lo);
    cudaGetSymbolAddress((void**)&whi,  g_whi);
    cudaGetSymbolAddress((void**)&wlo,  g_wlo);

    cudaFuncSetAttribute(mma_gemm,  cudaFuncAttributeMaxDynamicSharedMemorySize, MMA_SMEM2);
    cudaFuncSetAttribute(qkvs_gemm, cudaFuncAttributeMaxDynamicSharedMemorySize, MMA_SMEM2);

    cudaStream_t s = 0;
    #define WHI(i) (whi + (i) * 16384)
    #define WLO(i) (wlo + (i) * 16384)

    int gblocks = (N_NODES + 127) / 128;
    int ablocks = (N_NODES * 32 + 127) / 128;

    // 1: all splits + deg zero
    WPtrs wp;
    const float* wsrc[14] = {Wq1, Wk1, Wv1, Ws1, M1a, M1b, Wq2, Wk2, Wv2, Ws2, M2a, M2b, Wf1, Wf2};
    for (int i = 0; i < 14; i++) wp.p[i] = wsrc[i];
    bigsplit_kernel<<<WSPLIT_BLOCKS + ZERO_BLOCKS + XSPLIT_BLOCKS, 256, 0, s>>>(wp, x);
    // 2: hist
    hist_kernel<<<(N_EDGES + 255) / 256, 256, 0, s>>>(ei);
    // 3: scan stage 1
    scan_s1<<<SCAN_NBLK, 1024, 0, s>>>();
    // 4: layer-1 fused QKVS GEMM  (ncu capture slot)
    QkvsPtrs p1;
    for (int i = 0; i < 4; i++) { p1.bh[i] = WHI(i); p1.bl[i] = WLO(i); }
    p1.c[0] = q; p1.c[1] = k; p1.c[2] = v; p1.c[3] = sk;
    qkvs_gemm<<<dim3(gblocks, 4), 256, MMA_SMEM2, s>>>(xhi, xlo, p1, N_NODES);
    // 5-6: scan stages 2,3
    scan_s2<<<1, 64, 0, s>>>();
    scan_s3<<<(N_NODES + 255) / 256, 256, 0, s>>>();
    // 7: scatter
    scatter_kernel<<<(N_EDGES + 255) / 256, 256, 0, s>>>(ei, attr);

    // layer 1
    attn_kernel<<<ablocks, 128, 0, s>>>(q, k, v, sk, We1, h, hhi, hlo);
    run_mm(s, hhi,  hlo,  WHI(4), WLO(4), b1a, nullptr, t1, t1hi, t1lo, N_NODES, HID, 1);
    run_mm(s, t1hi, t1lo, WHI(5), WLO(5), b1b, h,       t2, t2hi, t2lo, N_NODES, HID, 1);

    // layer 2
    QkvsPtrs p2;
    for (int i = 0; i < 4; i++) { p2.bh[i] = WHI(6 + i); p2.bl[i] = WLO(6 + i); }
    p2.c[0] = q; p2.c[1] = k; p2.c[2] = v; p2.c[3] = sk;
    qkvs_gemm<<<dim3(gblocks, 4), 256, MMA_SMEM2, s>>>(t2hi, t2lo, p2, N_NODES);
    attn_kernel<<<ablocks, 128, 0, s>>>(q, k, v, sk, We2, h, hhi, hlo);
    run_mm(s, hhi,  hlo,  WHI(10), WLO(10), b2a, nullptr, t1, t1hi, t1lo, N_NODES, HID, 1);
    run_mm(s, t1hi, t1lo, WHI(11), WLO(11), b2b, h,       t2, t2hi, t2lo, N_NODES, HID, 1);

    // final MLP
    run_mm(s, t2hi, t2lo, WHI(12), WLO(12), bf1, nullptr, t1, t1hi, t1lo, N_NODES, HID, 1);
    run_mm(s, t1hi, t1lo, WHI(13), WLO(13), bf2, nullptr, out, nullptr, nullptr, N_NODES, OUTD, 1);
}

// round 10
// speedup vs baseline: 1.2568x; 1.0423x over previous
#include <cuda_runtime.h>
#include <cuda_bf16.h>
#include <math.h>
#include <stdint.h>

#define N_NODES 50000
#define N_EDGES 800000
#define HID     128
#define NHEAD   4
#define DH      32
#define OUTD    64

// ======================= scratch (device globals) ===========================
__device__ float g_q [N_NODES * HID];
__device__ float g_k [N_NODES * HID];
__device__ float g_v [N_NODES * HID];
__device__ float g_sk[N_NODES * HID];
__device__ float g_h [N_NODES * HID];
__device__ float g_t1[N_NODES * HID];
__device__ float g_t2[N_NODES * HID];
__device__ int   g_deg [N_NODES];
__device__ int   g_off [N_NODES + 1];
__device__ int   g_cur [N_NODES];
__device__ int   g_ssrc[N_EDGES];
__device__ float g_sattr[N_EDGES * 3];

#define SCAN_NBLK 49
__device__ int g_bsum[SCAN_NBLK];
__device__ int g_bpre[SCAN_NBLK];

__device__ __nv_bfloat16 g_xhi [N_NODES * HID];
__device__ __nv_bfloat16 g_xlo [N_NODES * HID];
__device__ __nv_bfloat16 g_hhi [N_NODES * HID];
__device__ __nv_bfloat16 g_hlo [N_NODES * HID];
__device__ __nv_bfloat16 g_t1hi[N_NODES * HID];
__device__ __nv_bfloat16 g_t1lo[N_NODES * HID];
__device__ __nv_bfloat16 g_t2hi[N_NODES * HID];
__device__ __nv_bfloat16 g_t2lo[N_NODES * HID];
__device__ __nv_bfloat16 g_whi[14 * 16384];
__device__ __nv_bfloat16 g_wlo[14 * 16384];

// ============ fused: weight split + deg zero + x split (one launch) =========
struct WPtrs { const float* p[14]; };

#define WSPLIT_BLOCKS 864
#define ZERO_BLOCKS   196
#define XSPLIT_BLOCKS 25000

__global__ void bigsplit_kernel(WPtrs wp, const float* __restrict__ x) {
    int b = blockIdx.x;
    if (b < WSPLIT_BLOCKS) {
        int mi, cb;
        if (b < 832) { mi = b >> 6; cb = b & 63; }
        else         { mi = 13;     cb = b - 832; }
        int i = cb * 256 + threadIdx.x;
        int n = (mi == 13) ? 8192 : 16384;
        if (i < n) {
            float v = wp.p[mi][i];
            __nv_bfloat16 h = __float2bfloat16(v);
            g_whi[mi * 16384 + i] = h;
            g_wlo[mi * 16384 + i] = __float2bfloat16(v - __bfloat162float(h));
        }
    } else if (b < WSPLIT_BLOCKS + ZERO_BLOCKS) {
        int i = (b - WSPLIT_BLOCKS) * 256 + threadIdx.x;
        if (i < N_NODES) g_deg[i] = 0;
    } else {
        int i = (b - WSPLIT_BLOCKS - ZERO_BLOCKS) * 256 + threadIdx.x;
        float v = x[i];
        __nv_bfloat16 h = __float2bfloat16(v);
        g_xhi[i] = h;
        g_xlo[i] = __float2bfloat16(v - __bfloat162float(h));
    }
}

// ======================= edge sorting =======================================
__global__ void hist_kernel(const int* __restrict__ ei) {
    int e = blockIdx.x * blockDim.x + threadIdx.x;
    if (e < N_EDGES) atomicAdd(&g_deg[ei[N_EDGES + e]], 1);
}

__global__ __launch_bounds__(1024) void scan_s1() {
    __shared__ int wsum[32];
    int tid = threadIdx.x, lane = tid & 31, wid = tid >> 5;
    int i = blockIdx.x * 1024 + tid;
    int v = (i < N_NODES) ? g_deg[i] : 0;
    int x = v;
    #pragma unroll
    for (int d = 1; d < 32; d <<= 1) {
        int y = __shfl_up_sync(0xffffffffu, x, d);
        if (lane >= d) x += y;
    }
    if (lane == 31) wsum[wid] = x;
    __syncthreads();
    if (wid == 0) {
        int s = wsum[lane];
        #pragma unroll
        for (int d = 1; d < 32; d <<= 1) {
            int y = __shfl_up_sync(0xffffffffu, s, d);
            if (lane >= d) s += y;
        }
        wsum[lane] = s;
    }
    __syncthreads();
    int incl = x + (wid > 0 ? wsum[wid - 1] : 0);
    if (i < N_NODES) g_off[i] = incl - v;
    if (tid == 1023) g_bsum[blockIdx.x] = incl;
}

__global__ void scan_s2() {
    __shared__ int w0sum;
    int tid = threadIdx.x;
    int lane = tid & 31, wid = tid >> 5;
    int v = (tid < SCAN_NBLK) ? g_bsum[tid] : 0;
    int x = v;
    #pragma unroll
    for (int d = 1; d < 32; d <<= 1) {
        int y = __shfl_up_sync(0xffffffffu, x, d);
        if (lane >= d) x += y;
    }
    if (wid == 0 && lane == 31) w0sum = x;
    __syncthreads();
    int incl = x + (wid ? w0sum : 0);
    if (tid < SCAN_NBLK) g_bpre[tid] = incl - v;
    if (tid == SCAN_NBLK - 1) g_off[N_NODES] = incl;
}

__global__ void scan_s3() {
    int i = blockIdx.x * blockDim.x + threadIdx.x;
    if (i < N_NODES) {
        int o = g_off[i] + g_bpre[i >> 10];
        g_off[i] = o;
        g_cur[i] = o;
    }
}

__global__ void scatter_kernel(const int* __restrict__ ei, const float* __restrict__ attr) {
    int e = blockIdx.x * blockDim.x + threadIdx.x;
    if (e < N_EDGES) {
        int dst = ei[N_EDGES + e];
        int pos = atomicAdd(&g_cur[dst], 1);
        g_ssrc[pos] = ei[e];
        g_sattr[3 * pos + 0] = attr[3 * e + 0];
        g_sattr[3 * pos + 1] = attr[3 * e + 1];
        g_sattr[3 * pos + 2] = attr[3 * e + 2];
    }
}

// ======================= GELU ==============================================
__device__ __forceinline__ float gelu_f(float x) {
    float x3 = x * x * x;
    float u = 0.7978845608028654f * (x + 0.044715f * x3);
    return 0.5f * x * (1.0f + tanhf(u));
}

// ======================= HMMA GEMM common ===================================
#define SROW2 72

__device__ __forceinline__ void mma16816(float* c,
    uint32_t a0, uint32_t a1, uint32_t a2, uint32_t a3,
    uint32_t b0, uint32_t b1) {
    asm volatile(
        "mma.sync.aligned.m16n8k16.row.col.f32.bf16.bf16.f32 "
        "{%0,%1,%2,%3}, {%4,%5,%6,%7}, {%8,%9}, {%0,%1,%2,%3};"
        : "+f"(c[0]), "+f"(c[1]), "+f"(c[2]), "+f"(c[3])
        : "r"(a0), "r"(a1), "r"(a2), "r"(a3), "r"(b0), "r"(b1));
}

__device__ __forceinline__ void ldsm_x4(uint32_t& r0, uint32_t& r1,
                                        uint32_t& r2, uint32_t& r3, uint32_t addr) {
    asm volatile("ldmatrix.sync.aligned.m8n8.x4.shared.b16 {%0,%1,%2,%3}, [%4];"
                 : "=r"(r0), "=r"(r1), "=r"(r2), "=r"(r3) : "r"(addr));
}

__device__ __forceinline__ uint32_t smem_u32(const void* p) {
    return (uint32_t)__cvta_generic_to_shared(p);
}

// stage one K=64 slab of A, 128 rows (256 threads: 2/row, 4 uint4 each)
__device__ __forceinline__ void stage_slab_A128(
    const __nv_bfloat16* Ahi, const __nv_bfloat16* Alo,
    __nv_bfloat16* sAh, __nv_bfloat16* sAl, int m0, int M, int slab, int tid)
{
    int row = tid >> 1;
    int u0  = (tid & 1) * 4;
    int gr  = m0 + row;
    bool ok = gr < M;
    const uint4* ah = (const uint4*)(Ahi + (size_t)gr * 128 + slab * 64);
    const uint4* al = (const uint4*)(Alo + (size_t)gr * 128 + slab * 64);
    uint4 z = make_uint4(0u, 0u, 0u, 0u);
    #pragma unroll
    for (int u = u0; u < u0 + 4; u++) {
        *(uint4*)(&sAh[row * SROW2 + u * 8]) = ok ? ah[u] : z;
        *(uint4*)(&sAl[row * SROW2 + u * 8]) = ok ? al[u] : z;
    }
}

// stage one K=64 slab of A, 64 rows (256 threads: 4/row, 2 uint4 each)
__device__ __forceinline__ void stage_slab_A64(
    const __nv_bfloat16* Ahi, const __nv_bfloat16* Alo,
    __nv_bfloat16* sAh, __nv_bfloat16* sAl, int m0, int M, int slab, int tid)
{
    int row = tid >> 2;
    int u0  = (tid & 3) * 2;
    int gr  = m0 + row;
    bool ok = gr < M;
    const uint4* ah = (const uint4*)(Ahi + (size_t)gr * 128 + slab * 64);
    const uint4* al = (const uint4*)(Alo + (size_t)gr * 128 + slab * 64);
    uint4 z = make_uint4(0u, 0u, 0u, 0u);
    #pragma unroll
    for (int u = u0; u < u0 + 2; u++) {
        *(uint4*)(&sAh[row * SROW2 + u * 8]) = ok ? ah[u] : z;
        *(uint4*)(&sAl[row * SROW2 + u * 8]) = ok ? al[u] : z;
    }
}

__device__ __forceinline__ void stage_slab_B(
    const __nv_bfloat16* Bhi, const __nv_bfloat16* Blo,
    __nv_bfloat16* sBh, __nv_bfloat16* sBl, int Nout, int slab, int tid)
{
    int row = tid >> 1;
    if (row < Nout) {
        int u0 = (tid & 1) * 4;
        const uint4* bh = (const uint4*)(Bhi + (size_t)row * 128 + slab * 64);
        const uint4* bl = (const uint4*)(Blo + (size_t)row * 128 + slab * 64);
        #pragma unroll
        for (int u = u0; u < u0 + 4; u++) {
            *(uint4*)(&sBh[row * SROW2 + u * 8]) = bh[u];
            *(uint4*)(&sBl[row * SROW2 + u * 8]) = bl[u];
        }
    }
}

// one K=64 slab of mainloop; warp tile 32 x (8*ntN), ntN even
__device__ __forceinline__ void mainloop_slab(
    const __nv_bfloat16* sAh, const __nv_bfloat16* sAl,
    const __nv_bfloat16* sBh, const __nv_bfloat16* sBl,
    float acc[2][8][4], int mt, int lane, int ntBeg, int ntN)
{
    uint32_t aAh = smem_u32(sAh), aAl = smem_u32(sAl);
    uint32_t aBh = smem_u32(sBh), aBl = smem_u32(sBl);
    int arow = lane & 15, akh = 8 * (lane >> 4);
    int brow = lane & 7;
    int bsel = lane >> 4;
    int bk   = 8 * ((lane >> 3) & 1);

    for (int kt = 0; kt < 64; kt += 16) {
        uint32_t ah[2][4], al[2][4];
        #pragma unroll
        for (int mi = 0; mi < 2; mi++) {
            int aoff = (mt + mi * 16 + arow) * SROW2 + akh + kt;
            ldsm_x4(ah[mi][0], ah[mi][1], ah[mi][2], ah[mi][3], aAh + (uint32_t)aoff * 2);
            ldsm_x4(al[mi][0], al[mi][1], al[mi][2], al[mi][3], aAl + (uint32_t)aoff * 2);
        }
        #pragma unroll
        for (int p = 0; p < 4; p++) {
            if (2 * p >= ntN) break;
            int nt = ntBeg + 2 * p + bsel;
            int boff = (nt * 8 + brow) * SROW2 + bk + kt;
            uint32_t bh0, bh1, bh2, bh3, bl0, bl1, bl2, bl3;
            ldsm_x4(bh0, bh1, bh2, bh3, aBh + (uint32_t)boff * 2);
            ldsm_x4(bl0, bl1, bl2, bl3, aBl + (uint32_t)boff * 2);
            #pragma unroll
            for (int mi = 0; mi < 2; mi++) {
                mma16816(acc[mi][2 * p + 0], ah[mi][0], ah[mi][1], ah[mi][2], ah[mi][3], bh0, bh1);
                mma16816(acc[mi][2 * p + 0], ah[mi][0], ah[mi][1], ah[mi][2], ah[mi][3], bl0, bl1);
                mma16816(acc[mi][2 * p + 0], al[mi][0], al[mi][1], al[mi][2], al[mi][3], bh0, bh1);
                mma16816(acc[mi][2 * p + 1], ah[mi][0], ah[mi][1], ah[mi][2], ah[mi][3], bh2, bh3);
                mma16816(acc[mi][2 * p + 1], ah[mi][0], ah[mi][1], ah[mi][2], ah[mi][3], bl2, bl3);
                mma16816(acc[mi][2 * p + 1], al[mi][0], al[mi][1], al[mi][2], al[mi][3], bh2, bh3);
            }
        }
    }
}

// ======================= mma_gemm: 64-row CTAs (wave-quantization fix) ======
// smem: A 64x72x2B x2 = 18432, B 128x72x2B x2 = 36864 -> 55296 B/CTA
#define OFF3_AH 0
#define OFF3_AL 9216
#define OFF3_BH 18432
#define OFF3_BL 36864
#define MMA_SMEM3 55296

__global__ __launch_bounds__(256, 2) void mma_gemm(
    const __nv_bfloat16* __restrict__ Ahi, const __nv_bfloat16* __restrict__ Alo,
    const __nv_bfloat16* __restrict__ Bhi, const __nv_bfloat16* __restrict__ Blo,
    const float* __restrict__ bias, const float* __restrict__ res,
    float* __restrict__ C, __nv_bfloat16* __restrict__ Chi, __nv_bfloat16* __restrict__ Clo,
    int M, int Nout, int act)
{
    extern __shared__ char smem[];
    __nv_bfloat16* sAh = (__nv_bfloat16*)(smem + OFF3_AH);
    __nv_bfloat16* sAl = (__nv_bfloat16*)(smem + OFF3_AL);
    __nv_bfloat16* sBh = (__nv_bfloat16*)(smem + OFF3_BH);
    __nv_bfloat16* sBl = (__nv_bfloat16*)(smem + OFF3_BL);
    int tid = threadIdx.x;
    int m0 = blockIdx.x * 64;

    int lane = tid & 31, wid = tid >> 5;
    int grp = lane >> 2, qd = lane & 3;
    int mt = (wid >> 2) * 32;             // 2 m-slots of 32 rows
    int NT = Nout >> 3;
    int ntBeg = (wid & 3) * (NT >> 2);    // 4-way n split
    int ntN   = NT >> 2;                  // 4 (Nout=128) or 2 (Nout=64)

    float acc[2][8][4];
    #pragma unroll
    for (int mi = 0; mi < 2; mi++)
        #pragma unroll
        for (int i = 0; i < 8; i++)
            #pragma unroll
            for (int j = 0; j < 4; j++) acc[mi][i][j] = 0.f;

    #pragma unroll
    for (int s = 0; s < 2; s++) {
        if (s) __syncthreads();
        stage_slab_A64(Ahi, Alo, sAh, sAl, m0, M, s, tid);
        stage_slab_B(Bhi, Blo, sBh, sBl, Nout, s, tid);
        __syncthreads();
        mainloop_slab(sAh, sAl, sBh, sBl, acc, mt, lane, ntBeg, ntN);
    }

    #pragma unroll
    for (int mi = 0; mi < 2; mi++) {
        #pragma unroll
        for (int t = 0; t < 8; t++) {
            if (t >= ntN) break;
            int col = (ntBeg + t) * 8 + 2 * qd;
            float bsum0 = bias ? bias[col]     : 0.f;
            float bsum1 = bias ? bias[col + 1] : 0.f;
            #pragma unroll
            for (int half = 0; half < 2; half++) {
                int row = m0 + mt + mi * 16 + grp + half * 8;
                if (row >= M) continue;
                float v0 = acc[mi][t][half * 2 + 0] + bsum0;
                float v1 = acc[mi][t][half * 2 + 1] + bsum1;
                if (act) { v0 = gelu_f(v0); v1 = gelu_f(v1); }
                size_t base = (size_t)row * Nout + col;
                if (res) { v0 += res[base]; v1 += res[base + 1]; }
                *(float2*)(C + base) = make_float2(v0, v1);
                if (Chi) {
                    __nv_bfloat16 h0 = __float2bfloat16(v0);
                    __nv_bfloat16 h1 = __float2bfloat16(v1);
                    __nv_bfloat162 hh; hh.x = h0; hh.y = h1;
                    __nv_bfloat162 ll;
                    ll.x = __float2bfloat16(v0 - __bfloat162float(h0));
                    ll.y = __float2bfloat16(v1 - __bfloat162float(h1));
                    *(__nv_bfloat162*)(Chi + base) = hh;
                    *(__nv_bfloat162*)(Clo + base) = ll;
                }
            }
        }
    }
}

// ======================= qkvs_gemm: 128-row CTAs, 2 CTAs/SM =================
#define OFF2_AH 0
#define OFF2_AL 18432
#define OFF2_BH 36864
#define OFF2_BL 55296
#define MMA_SMEM2 73728

struct QkvsPtrs {
    const __nv_bfloat16 *bh[4], *bl[4];
    float* c[4];
};

__global__ __launch_bounds__(256, 2) void qkvs_gemm(
    const __nv_bfloat16* __restrict__ Ahi, const __nv_bfloat16* __restrict__ Alo,
    QkvsPtrs pp, int M)
{
    extern __shared__ char smem[];
    __nv_bfloat16* sAh = (__nv_bfloat16*)(smem + OFF2_AH);
    __nv_bfloat16* sAl = (__nv_bfloat16*)(smem + OFF2_AL);
    __nv_bfloat16* sBh = (__nv_bfloat16*)(smem + OFF2_BH);
    __nv_bfloat16* sBl = (__nv_bfloat16*)(smem + OFF2_BL);
    int tid = threadIdx.x;
    int m0 = blockIdx.x * 128;
    int sel = blockIdx.y;

    int lane = tid & 31, wid = tid >> 5;
    int grp = lane >> 2, qd = lane & 3;
    int mt = (wid >> 1) * 32;
    int ntBeg = (wid & 1) * 8;

    float acc[2][8][4];
    #pragma unroll
    for (int mi = 0; mi < 2; mi++)
        #pragma unroll
        for (int i = 0; i < 8; i++)
            #pragma unroll
            for (int j = 0; j < 4; j++) acc[mi][i][j] = 0.f;

    #pragma unroll
    for (int s = 0; s < 2; s++) {
        if (s) __syncthreads();
        stage_slab_A128(Ahi, Alo, sAh, sAl, m0, M, s, tid);
        stage_slab_B(pp.bh[sel], pp.bl[sel], sBh, sBl, HID, s, tid);
        __syncthreads();
        mainloop_slab(sAh, sAl, sBh, sBl, acc, mt, lane, ntBeg, 8);
    }

    float* C = pp.c[sel];
    #pragma unroll
    for (int mi = 0; mi < 2; mi++) {
        #pragma unroll
        for (int t = 0; t < 8; t++) {
            int col = (ntBeg + t) * 8 + 2 * qd;
            #pragma unroll
            for (int half = 0; half < 2; half++) {
                int row = m0 + mt + mi * 16 + grp + half * 8;
                if (row >= M) continue;
                size_t base = (size_t)row * HID + col;
                *(float2*)(C + base) = make_float2(acc[mi][t][half * 2], acc[mi][t][half * 2 + 1]);
            }
        }
    }
}

// ======================= edge attention =====================================
__global__ __launch_bounds__(128) void attn_kernel(
    const float* __restrict__ q, const float* __restrict__ k,
    const float* __restrict__ v, const float* __restrict__ skip,
    const float* __restrict__ We, float* __restrict__ out,
    __nv_bfloat16* __restrict__ outhi, __nv_bfloat16* __restrict__ outlo)
{
    __shared__ float we_s[HID * 3];
    int tid = threadIdx.x;
    for (int i = tid; i < HID * 3; i += blockDim.x) we_s[i] = We[i];
    __syncthreads();

    int warp = blockIdx.x * (blockDim.x >> 5) + (tid >> 5);
    if (warp >= N_NODES) return;
    int lane = tid & 31;
    int col  = (lane >> 3) * DH + (lane & 7) * 4;

    float wr[12];
    #pragma unroll
    for (int i = 0; i < 4; i++)
        #pragma unroll
        for (int c = 0; c < 3; c++)
            wr[i * 3 + c] = we_s[3 * (col + i) + c];

    float4 qv = *(const float4*)(q + (size_t)warp * HID + col);
    float m = -INFINITY, ssum = 0.f;
    float ox = 0.f, oy = 0.f, oz = 0.f, ow = 0.f;

    int e0 = g_off[warp], e1 = g_off[warp + 1];
    for (int e = e0; e < e1; e++) {
        int src = g_ssrc[e];
        float a0 = g_sattr[3 * e + 0];
        float a1 = g_sattr[3 * e + 1];
        float a2 = g_sattr[3 * e + 2];
        float4 kv = *(const float4*)(k + (size_t)src * HID + col);
        float4 vv = *(const float4*)(v + (size_t)src * HID + col);
        float ec0 = fmaf(a0, wr[0], fmaf(a1, wr[1],  a2 * wr[2]));
        float ec1 = fmaf(a0, wr[3], fmaf(a1, wr[4],  a2 * wr[5]));
        float ec2 = fmaf(a0, wr[6], fmaf(a1, wr[7],  a2 * wr[8]));
        float ec3 = fmaf(a0, wr[9], fmaf(a1, wr[10], a2 * wr[11]));
        float kx = kv.x + ec0, ky = kv.y + ec1, kz = kv.z + ec2, kw = kv.w + ec3;
        float dot = qv.x * kx + qv.y * ky + qv.z * kz + qv.w * kw;
        dot += __shfl_xor_sync(0xffffffffu, dot, 1);
        dot += __shfl_xor_sync(0xffffffffu, dot, 2);
        dot += __shfl_xor_sync(0xffffffffu, dot, 4);
        float alpha = dot * 0.17677669529663687f;
        float nm = fmaxf(m, alpha);
        float sc = __expf(m - nm);
        float p  = __expf(alpha - nm);
        ssum = ssum * sc + p;
        ox = ox * sc + p * (vv.x + ec0);
        oy = oy * sc + p * (vv.y + ec1);
        oz = oz * sc + p * (vv.z + ec2);
        ow = ow * sc + p * (vv.w + ec3);
        m = nm;
    }
    float inv = 1.0f / fmaxf(ssum, 1e-16f);
    float4 sk = *(const float4*)(skip + (size_t)warp * HID + col);
    float o0 = ox * inv + sk.x, o1 = oy * inv + sk.y;
    float o2 = oz * inv + sk.z, o3 = ow * inv + sk.w;
    size_t base = (size_t)warp * HID + col;
    *(float4*)(out + base) = make_float4(o0, o1, o2, o3);

    float vs[4] = {o0, o1, o2, o3};
    #pragma unroll
    for (int pr = 0; pr < 2; pr++) {
        float v0 = vs[pr * 2], v1 = vs[pr * 2 + 1];
        __nv_bfloat16 h0 = __float2bfloat16(v0);
        __nv_bfloat16 h1 = __float2bfloat16(v1);
        __nv_bfloat162 hh; hh.x = h0; hh.y = h1;
        __nv_bfloat162 ll;
        ll.x = __float2bfloat16(v0 - __bfloat162float(h0));
        ll.y = __float2bfloat16(v1 - __bfloat162float(h1));
        *(__nv_bfloat162*)(outhi + base + pr * 2) = hh;
        *(__nv_bfloat162*)(outlo + base + pr * 2) = ll;
    }
}

// ======================= launch =============================================
static inline void run_mm(cudaStream_t s,
                          const __nv_bfloat16* Ahi, const __nv_bfloat16* Alo,
                          const __nv_bfloat16* Bhi, const __nv_bfloat16* Blo,
                          const float* bias, const float* res,
                          float* C, __nv_bfloat16* Chi, __nv_bfloat16* Clo,
                          int M, int Nout, int act) {
    int grid = (M + 63) / 64;
    mma_gemm<<<grid, 256, MMA_SMEM3, s>>>(Ahi, Alo, Bhi, Blo, bias, res, C, Chi, Clo, M, Nout, act);
}

extern "C" void kernel_launch(void* const* d_in, const int* in_sizes, int n_in,
                              void* d_out, int out_size) {
    const float* x    = (const float*)d_in[0];
    const int*   ei   = (const int*)  d_in[1];
    const float* attr = (const float*)d_in[2];
    const float* Wq1 = (const float*)d_in[3],  *Wk1 = (const float*)d_in[4];
    const float* Wv1 = (const float*)d_in[5],  *We1 = (const float*)d_in[6];
    const float* Ws1 = (const float*)d_in[7];
    const float* M1a = (const float*)d_in[8],  *b1a = (const float*)d_in[9];
    const float* M1b = (const float*)d_in[10], *b1b = (const float*)d_in[11];
    const float* Wq2 = (const float*)d_in[12], *Wk2 = (const float*)d_in[13];
    const float* Wv2 = (const float*)d_in[14], *We2 = (const float*)d_in[15];
    const float* Ws2 = (const float*)d_in[16];
    const float* M2a = (const float*)d_in[17], *b2a = (const float*)d_in[18];
    const float* M2b = (const float*)d_in[19], *b2b = (const float*)d_in[20];
    const float* Wf1 = (const float*)d_in[21], *bf1 = (const float*)d_in[22];
    const float* Wf2 = (const float*)d_in[23], *bf2 = (const float*)d_in[24];
    float* out = (float*)d_out;

    float *q, *k, *v, *sk, *h, *t1, *t2;
    cudaGetSymbolAddress((void**)&q,  g_q);
    cudaGetSymbolAddress((void**)&k,  g_k);
    cudaGetSymbolAddress((void**)&v,  g_v);
    cudaGetSymbolAddress((void**)&sk, g_sk);
    cudaGetSymbolAddress((void**)&h,  g_h);
    cudaGetSymbolAddress((void**)&t1, g_t1);
    cudaGetSymbolAddress((void**)&t2, g_t2);

    __nv_bfloat16 *xhi, *xlo, *hhi, *hlo, *t1hi, *t1lo, *t2hi, *t2lo, *whi, *wlo;
    cudaGetSymbolAddress((void**)&xhi,  g_xhi);
    cudaGetSymbolAddress((void**)&xlo,  g_xlo);
    cudaGetSymbolAddress((void**)&hhi,  g_hhi);
    cudaGetSymbolAddress((void**)&hlo,  g_hlo);
    cudaGetSymbolAddress((void**)&t1hi, g_t1hi);
    cudaGetSymbolAddress((void**)&t1lo, g_t1lo);
    cudaGetSymbolAddress((void**)&t2hi, g_t2hi);
    cudaGetSymbolAddress((void**)&t2lo, g_t2lo);
    cudaGetSymbolAddress((void**)&whi,  g_whi);
    cudaGetSymbolAddress((void**)&wlo,  g_wlo);

    cudaFuncSetAttribute(mma_gemm,  cudaFuncAttributeMaxDynamicSharedMemorySize, MMA_SMEM3);
    cudaFuncSetAttribute(qkvs_gemm, cudaFuncAttributeMaxDynamicSharedMemorySize, MMA_SMEM2);

    cudaStream_t s = 0;
    #define WHI(i) (whi + (i) * 16384)
    #define WLO(i) (wlo + (i) * 16384)

    int gblocks = (N_NODES + 127) / 128;
    int ablocks = (N_NODES * 32 + 127) / 128;

    // 1: all splits + deg zero
    WPtrs wp;
    const float* wsrc[14] = {Wq1, Wk1, Wv1, Ws1, M1a, M1b, Wq2, Wk2, Wv2, Ws2, M2a, M2b, Wf1, Wf2};
    for (int i = 0; i < 14; i++) wp.p[i] = wsrc[i];
    bigsplit_kernel<<<WSPLIT_BLOCKS + ZERO_BLOCKS + XSPLIT_BLOCKS, 256, 0, s>>>(wp, x);
    // 2: hist
    hist_kernel<<<(N_EDGES + 255) / 256, 256, 0, s>>>(ei);
    // 3: scan stage 1
    scan_s1<<<SCAN_NBLK, 1024, 0, s>>>();
    // 4: layer-1 fused QKVS GEMM  (ncu capture slot)
    QkvsPtrs p1;
    for (int i = 0; i < 4; i++) { p1.bh[i] = WHI(i); p1.bl[i] = WLO(i); }
    p1.c[0] = q; p1.c[1] = k; p1.c[2] = v; p1.c[3] = sk;
    qkvs_gemm<<<dim3(gblocks, 4), 256, MMA_SMEM2, s>>>(xhi, xlo, p1, N_NODES);
    // 5-6: scan stages 2,3
    scan_s2<<<1, 64, 0, s>>>();
    scan_s3<<<(N_NODES + 255) / 256, 256, 0, s>>>();
    // 7: scatter
    scatter_kernel<<<(N_EDGES + 255) / 256, 256, 0, s>>>(ei, attr);

    // layer 1
    attn_kernel<<<ablocks, 128, 0, s>>>(q, k, v, sk, We1, h, hhi, hlo);
    run_mm(s, hhi,  hlo,  WHI(4), WLO(4), b1a, nullptr, t1, t1hi, t1lo, N_NODES, HID, 1);
    run_mm(s, t1hi, t1lo, WHI(5), WLO(5), b1b, h,       t2, t2hi, t2lo, N_NODES, HID, 1);

    // layer 2
    QkvsPtrs p2;
    for (int i = 0; i < 4; i++) { p2.bh[i] = WHI(6 + i); p2.bl[i] = WLO(6 + i); }
    p2.c[0] = q; p2.c[1] = k; p2.c[2] = v; p2.c[3] = sk;
    qkvs_gemm<<<dim3(gblocks, 4), 256, MMA_SMEM2, s>>>(t2hi, t2lo, p2, N_NODES);
    attn_kernel<<<ablocks, 128, 0, s>>>(q, k, v, sk, We2, h, hhi, hlo);
    run_mm(s, hhi,  hlo,  WHI(10), WLO(10), b2a, nullptr, t1, t1hi, t1lo, N_NODES, HID, 1);
    run_mm(s, t1hi, t1lo, WHI(11), WLO(11), b2b, h,       t2, t2hi, t2lo, N_NODES, HID, 1);

    // final MLP
    run_mm(s, t2hi, t2lo, WHI(12), WLO(12), bf1, nullptr, t1, t1hi, t1lo, N_NODES, HID, 1);
    run_mm(s, t1hi, t1lo, WHI(13), WLO(13), bf2, nullptr, out, nullptr, nullptr, N_NODES, OUTD, 1);
}

// round 11
// speedup vs baseline: 1.2582x; 1.0011x over previous
#include <cuda_runtime.h>
#include <cuda_bf16.h>
#include <math.h>
#include <stdint.h>

#define N_NODES 50000
#define N_EDGES 800000
#define HID     128
#define NHEAD   4
#define DH      32
#define OUTD    64

// ======================= scratch (device globals) ===========================
__device__ float g_q [N_NODES * HID];
__device__ float g_k [N_NODES * HID];
__device__ float g_v [N_NODES * HID];
__device__ float g_sk[N_NODES * HID];
__device__ float g_h [N_NODES * HID];
__device__ float g_t1[N_NODES * HID];
__device__ float g_t2[N_NODES * HID];
__device__ int   g_deg [N_NODES];
__device__ int   g_off [N_NODES + 1];
__device__ int   g_cur [N_NODES];
__device__ int   g_ssrc[N_EDGES];
__device__ float g_sattr[N_EDGES * 3];

#define SCAN_NBLK 49
__device__ int g_bsum[SCAN_NBLK];
__device__ int g_bpre[SCAN_NBLK];

__device__ __nv_bfloat16 g_xhi [N_NODES * HID];
__device__ __nv_bfloat16 g_xlo [N_NODES * HID];
__device__ __nv_bfloat16 g_hhi [N_NODES * HID];
__device__ __nv_bfloat16 g_hlo [N_NODES * HID];
__device__ __nv_bfloat16 g_t1hi[N_NODES * HID];
__device__ __nv_bfloat16 g_t1lo[N_NODES * HID];
__device__ __nv_bfloat16 g_t2hi[N_NODES * HID];
__device__ __nv_bfloat16 g_t2lo[N_NODES * HID];
__device__ __nv_bfloat16 g_whi[14 * 16384];
__device__ __nv_bfloat16 g_wlo[14 * 16384];

// ============ fused: weight split + x split (one launch, NO deg zero) =======
struct WPtrs { const float* p[14]; };

#define WSPLIT_BLOCKS 864
#define XSPLIT_BLOCKS 25000

__global__ void bigsplit_kernel(WPtrs wp, const float* __restrict__ x) {
    int b = blockIdx.x;
    if (b < WSPLIT_BLOCKS) {
        int mi, cb;
        if (b < 832) { mi = b >> 6; cb = b & 63; }
        else         { mi = 13;     cb = b - 832; }
        int i = cb * 256 + threadIdx.x;
        int n = (mi == 13) ? 8192 : 16384;
        if (i < n) {
            float v = wp.p[mi][i];
            __nv_bfloat16 h = __float2bfloat16(v);
            g_whi[mi * 16384 + i] = h;
            g_wlo[mi * 16384 + i] = __float2bfloat16(v - __bfloat162float(h));
        }
    } else {
        int i = (b - WSPLIT_BLOCKS) * 256 + threadIdx.x;
        float v = x[i];
        __nv_bfloat16 h = __float2bfloat16(v);
        g_xhi[i] = h;
        g_xlo[i] = __float2bfloat16(v - __bfloat162float(h));
    }
}

// ======================= edge sorting =======================================
__global__ void zero_deg_kernel() {
    int i = blockIdx.x * blockDim.x + threadIdx.x;
    if (i < N_NODES) g_deg[i] = 0;
}

__global__ void hist_kernel(const int* __restrict__ ei) {
    int e = blockIdx.x * blockDim.x + threadIdx.x;
    if (e < N_EDGES) atomicAdd(&g_deg[ei[N_EDGES + e]], 1);
}

__global__ __launch_bounds__(1024) void scan_s1() {
    __shared__ int wsum[32];
    int tid = threadIdx.x, lane = tid & 31, wid = tid >> 5;
    int i = blockIdx.x * 1024 + tid;
    int v = (i < N_NODES) ? g_deg[i] : 0;
    int x = v;
    #pragma unroll
    for (int d = 1; d < 32; d <<= 1) {
        int y = __shfl_up_sync(0xffffffffu, x, d);
        if (lane >= d) x += y;
    }
    if (lane == 31) wsum[wid] = x;
    __syncthreads();
    if (wid == 0) {
        int s = wsum[lane];
        #pragma unroll
        for (int d = 1; d < 32; d <<= 1) {
            int y = __shfl_up_sync(0xffffffffu, s, d);
            if (lane >= d) s += y;
        }
        wsum[lane] = s;
    }
    __syncthreads();
    int incl = x + (wid > 0 ? wsum[wid - 1] : 0);
    if (i < N_NODES) g_off[i] = incl - v;
    if (tid == 1023) g_bsum[blockIdx.x] = incl;
}

__global__ void scan_s2() {
    __shared__ int w0sum;
    int tid = threadIdx.x;
    int lane = tid & 31, wid = tid >> 5;
    int v = (tid < SCAN_NBLK) ? g_bsum[tid] : 0;
    int x = v;
    #pragma unroll
    for (int d = 1; d < 32; d <<= 1) {
        int y = __shfl_up_sync(0xffffffffu, x, d);
        if (lane >= d) x += y;
    }
    if (wid == 0 && lane == 31) w0sum = x;
    __syncthreads();
    int incl = x + (wid ? w0sum : 0);
    if (tid < SCAN_NBLK) g_bpre[tid] = incl - v;
    if (tid == SCAN_NBLK - 1) g_off[N_NODES] = incl;
}

__global__ void scan_s3() {
    int i = blockIdx.x * blockDim.x + threadIdx.x;
    if (i < N_NODES) {
        int o = g_off[i] + g_bpre[i >> 10];
        g_off[i] = o;
        g_cur[i] = o;
    }
}

__global__ void scatter_kernel(const int* __restrict__ ei, const float* __restrict__ attr) {
    int e = blockIdx.x * blockDim.x + threadIdx.x;
    if (e < N_EDGES) {
        int dst = ei[N_EDGES + e];
        int pos = atomicAdd(&g_cur[dst], 1);
        g_ssrc[pos] = ei[e];
        g_sattr[3 * pos + 0] = attr[3 * e + 0];
        g_sattr[3 * pos + 1] = attr[3 * e + 1];
        g_sattr[3 * pos + 2] = attr[3 * e + 2];
    }
}

// ======================= GELU ==============================================
__device__ __forceinline__ float gelu_f(float x) {
    float x3 = x * x * x;
    float u = 0.7978845608028654f * (x + 0.044715f * x3);
    return 0.5f * x * (1.0f + tanhf(u));
}

// ======================= HMMA GEMM common ===================================
#define SROW2 72

__device__ __forceinline__ void mma16816(float* c,
    uint32_t a0, uint32_t a1, uint32_t a2, uint32_t a3,
    uint32_t b0, uint32_t b1) {
    asm volatile(
        "mma.sync.aligned.m16n8k16.row.col.f32.bf16.bf16.f32 "
        "{%0,%1,%2,%3}, {%4,%5,%6,%7}, {%8,%9}, {%0,%1,%2,%3};"
        : "+f"(c[0]), "+f"(c[1]), "+f"(c[2]), "+f"(c[3])
        : "r"(a0), "r"(a1), "r"(a2), "r"(a3), "r"(b0), "r"(b1));
}

__device__ __forceinline__ void ldsm_x4(uint32_t& r0, uint32_t& r1,
                                        uint32_t& r2, uint32_t& r3, uint32_t addr) {
    asm volatile("ldmatrix.sync.aligned.m8n8.x4.shared.b16 {%0,%1,%2,%3}, [%4];"
                 : "=r"(r0), "=r"(r1), "=r"(r2), "=r"(r3) : "r"(addr));
}

__device__ __forceinline__ uint32_t smem_u32(const void* p) {
    return (uint32_t)__cvta_generic_to_shared(p);
}

__device__ __forceinline__ void stage_slab_A128(
    const __nv_bfloat16* Ahi, const __nv_bfloat16* Alo,
    __nv_bfloat16* sAh, __nv_bfloat16* sAl, int m0, int M, int slab, int tid)
{
    int row = tid >> 1;
    int u0  = (tid & 1) * 4;
    int gr  = m0 + row;
    bool ok = gr < M;
    const uint4* ah = (const uint4*)(Ahi + (size_t)gr * 128 + slab * 64);
    const uint4* al = (const uint4*)(Alo + (size_t)gr * 128 + slab * 64);
    uint4 z = make_uint4(0u, 0u, 0u, 0u);
    #pragma unroll
    for (int u = u0; u < u0 + 4; u++) {
        *(uint4*)(&sAh[row * SROW2 + u * 8]) = ok ? ah[u] : z;
        *(uint4*)(&sAl[row * SROW2 + u * 8]) = ok ? al[u] : z;
    }
}

__device__ __forceinline__ void stage_slab_A64(
    const __nv_bfloat16* Ahi, const __nv_bfloat16* Alo,
    __nv_bfloat16* sAh, __nv_bfloat16* sAl, int m0, int M, int slab, int tid)
{
    int row = tid >> 2;
    int u0  = (tid & 3) * 2;
    int gr  = m0 + row;
    bool ok = gr < M;
    const uint4* ah = (const uint4*)(Ahi + (size_t)gr * 128 + slab * 64);
    const uint4* al = (const uint4*)(Alo + (size_t)gr * 128 + slab * 64);
    uint4 z = make_uint4(0u, 0u, 0u, 0u);
    #pragma unroll
    for (int u = u0; u < u0 + 2; u++) {
        *(uint4*)(&sAh[row * SROW2 + u * 8]) = ok ? ah[u] : z;
        *(uint4*)(&sAl[row * SROW2 + u * 8]) = ok ? al[u] : z;
    }
}

__device__ __forceinline__ void stage_slab_B(
    const __nv_bfloat16* Bhi, const __nv_bfloat16* Blo,
    __nv_bfloat16* sBh, __nv_bfloat16* sBl, int Nout, int slab, int tid)
{
    int row = tid >> 1;
    if (row < Nout) {
        int u0 = (tid & 1) * 4;
        const uint4* bh = (const uint4*)(Bhi + (size_t)row * 128 + slab * 64);
        const uint4* bl = (const uint4*)(Blo + (size_t)row * 128 + slab * 64);
        #pragma unroll
        for (int u = u0; u < u0 + 4; u++) {
            *(uint4*)(&sBh[row * SROW2 + u * 8]) = bh[u];
            *(uint4*)(&sBl[row * SROW2 + u * 8]) = bl[u];
        }
    }
}

__device__ __forceinline__ void mainloop_slab(
    const __nv_bfloat16* sAh, const __nv_bfloat16* sAl,
    const __nv_bfloat16* sBh, const __nv_bfloat16* sBl,
    float acc[2][8][4], int mt, int lane, int ntBeg, int ntN)
{
    uint32_t aAh = smem_u32(sAh), aAl = smem_u32(sAl);
    uint32_t aBh = smem_u32(sBh), aBl = smem_u32(sBl);
    int arow = lane & 15, akh = 8 * (lane >> 4);
    int brow = lane & 7;
    int bsel = lane >> 4;
    int bk   = 8 * ((lane >> 3) & 1);

    for (int kt = 0; kt < 64; kt += 16) {
        uint32_t ah[2][4], al[2][4];
        #pragma unroll
        for (int mi = 0; mi < 2; mi++) {
            int aoff = (mt + mi * 16 + arow) * SROW2 + akh + kt;
            ldsm_x4(ah[mi][0], ah[mi][1], ah[mi][2], ah[mi][3], aAh + (uint32_t)aoff * 2);
            ldsm_x4(al[mi][0], al[mi][1], al[mi][2], al[mi][3], aAl + (uint32_t)aoff * 2);
        }
        #pragma unroll
        for (int p = 0; p < 4; p++) {
            if (2 * p >= ntN) break;
            int nt = ntBeg + 2 * p + bsel;
            int boff = (nt * 8 + brow) * SROW2 + bk + kt;
            uint32_t bh0, bh1, bh2, bh3, bl0, bl1, bl2, bl3;
            ldsm_x4(bh0, bh1, bh2, bh3, aBh + (uint32_t)boff * 2);
            ldsm_x4(bl0, bl1, bl2, bl3, aBl + (uint32_t)boff * 2);
            #pragma unroll
            for (int mi = 0; mi < 2; mi++) {
                mma16816(acc[mi][2 * p + 0], ah[mi][0], ah[mi][1], ah[mi][2], ah[mi][3], bh0, bh1);
                mma16816(acc[mi][2 * p + 0], ah[mi][0], ah[mi][1], ah[mi][2], ah[mi][3], bl0, bl1);
                mma16816(acc[mi][2 * p + 0], al[mi][0], al[mi][1], al[mi][2], al[mi][3], bh0, bh1);
                mma16816(acc[mi][2 * p + 1], ah[mi][0], ah[mi][1], ah[mi][2], ah[mi][3], bh2, bh3);
                mma16816(acc[mi][2 * p + 1], ah[mi][0], ah[mi][1], ah[mi][2], ah[mi][3], bl2, bl3);
                mma16816(acc[mi][2 * p + 1], al[mi][0], al[mi][1], al[mi][2], al[mi][3], bh2, bh3);
            }
        }
    }
}

// ======================= mma_gemm: 64-row CTAs ==============================
#define OFF3_AH 0
#define OFF3_AL 9216
#define OFF3_BH 18432
#define OFF3_BL 36864
#define MMA_SMEM3 55296

__global__ __launch_bounds__(256, 2) void mma_gemm(
    const __nv_bfloat16* __restrict__ Ahi, const __nv_bfloat16* __restrict__ Alo,
    const __nv_bfloat16* __restrict__ Bhi, const __nv_bfloat16* __restrict__ Blo,
    const float* __restrict__ bias, const float* __restrict__ res,
    float* __restrict__ C, __nv_bfloat16* __restrict__ Chi, __nv_bfloat16* __restrict__ Clo,
    int M, int Nout, int act)
{
    extern __shared__ char smem[];
    __nv_bfloat16* sAh = (__nv_bfloat16*)(smem + OFF3_AH);
    __nv_bfloat16* sAl = (__nv_bfloat16*)(smem + OFF3_AL);
    __nv_bfloat16* sBh = (__nv_bfloat16*)(smem + OFF3_BH);
    __nv_bfloat16* sBl = (__nv_bfloat16*)(smem + OFF3_BL);
    int tid = threadIdx.x;
    int m0 = blockIdx.x * 64;

    int lane = tid & 31, wid = tid >> 5;
    int grp = lane >> 2, qd = lane & 3;
    int mt = (wid >> 2) * 32;
    int NT = Nout >> 3;
    int ntBeg = (wid & 3) * (NT >> 2);
    int ntN   = NT >> 2;

    float acc[2][8][4];
    #pragma unroll
    for (int mi = 0; mi < 2; mi++)
        #pragma unroll
        for (int i = 0; i < 8; i++)
            #pragma unroll
            for (int j = 0; j < 4; j++) acc[mi][i][j] = 0.f;

    #pragma unroll
    for (int s = 0; s < 2; s++) {
        if (s) __syncthreads();
        stage_slab_A64(Ahi, Alo, sAh, sAl, m0, M, s, tid);
        stage_slab_B(Bhi, Blo, sBh, sBl, Nout, s, tid);
        __syncthreads();
        mainloop_slab(sAh, sAl, sBh, sBl, acc, mt, lane, ntBeg, ntN);
    }

    #pragma unroll
    for (int mi = 0; mi < 2; mi++) {
        #pragma unroll
        for (int t = 0; t < 8; t++) {
            if (t >= ntN) break;
            int col = (ntBeg + t) * 8 + 2 * qd;
            float bsum0 = bias ? bias[col]     : 0.f;
            float bsum1 = bias ? bias[col + 1] : 0.f;
            #pragma unroll
            for (int half = 0; half < 2; half++) {
                int row = m0 + mt + mi * 16 + grp + half * 8;
                if (row >= M) continue;
                float v0 = acc[mi][t][half * 2 + 0] + bsum0;
                float v1 = acc[mi][t][half * 2 + 1] + bsum1;
                if (act) { v0 = gelu_f(v0); v1 = gelu_f(v1); }
                size_t base = (size_t)row * Nout + col;
                if (res) { v0 += res[base]; v1 += res[base + 1]; }
                *(float2*)(C + base) = make_float2(v0, v1);
                if (Chi) {
                    __nv_bfloat16 h0 = __float2bfloat16(v0);
                    __nv_bfloat16 h1 = __float2bfloat16(v1);
                    __nv_bfloat162 hh; hh.x = h0; hh.y = h1;
                    __nv_bfloat162 ll;
                    ll.x = __float2bfloat16(v0 - __bfloat162float(h0));
                    ll.y = __float2bfloat16(v1 - __bfloat162float(h1));
                    *(__nv_bfloat162*)(Chi + base) = hh;
                    *(__nv_bfloat162*)(Clo + base) = ll;
                }
            }
        }
    }
}

// ======================= qkvs_gemm: 128-row CTAs, 2 CTAs/SM =================
#define OFF2_AH 0
#define OFF2_AL 18432
#define OFF2_BH 36864
#define OFF2_BL 55296
#define MMA_SMEM2 73728

struct QkvsPtrs {
    const __nv_bfloat16 *bh[4], *bl[4];
    float* c[4];
};

__global__ __launch_bounds__(256, 2) void qkvs_gemm(
    const __nv_bfloat16* __restrict__ Ahi, const __nv_bfloat16* __restrict__ Alo,
    QkvsPtrs pp, int M)
{
    extern __shared__ char smem[];
    __nv_bfloat16* sAh = (__nv_bfloat16*)(smem + OFF2_AH);
    __nv_bfloat16* sAl = (__nv_bfloat16*)(smem + OFF2_AL);
    __nv_bfloat16* sBh = (__nv_bfloat16*)(smem + OFF2_BH);
    __nv_bfloat16* sBl = (__nv_bfloat16*)(smem + OFF2_BL);
    int tid = threadIdx.x;
    int m0 = blockIdx.x * 128;
    int sel = blockIdx.y;

    int lane = tid & 31, wid = tid >> 5;
    int grp = lane >> 2, qd = lane & 3;
    int mt = (wid >> 1) * 32;
    int ntBeg = (wid & 1) * 8;

    float acc[2][8][4];
    #pragma unroll
    for (int mi = 0; mi < 2; mi++)
        #pragma unroll
        for (int i = 0; i < 8; i++)
            #pragma unroll
            for (int j = 0; j < 4; j++) acc[mi][i][j] = 0.f;

    #pragma unroll
    for (int s = 0; s < 2; s++) {
        if (s) __syncthreads();
        stage_slab_A128(Ahi, Alo, sAh, sAl, m0, M, s, tid);
        stage_slab_B(pp.bh[sel], pp.bl[sel], sBh, sBl, HID, s, tid);
        __syncthreads();
        mainloop_slab(sAh, sAl, sBh, sBl, acc, mt, lane, ntBeg, 8);
    }

    float* C = pp.c[sel];
    #pragma unroll
    for (int mi = 0; mi < 2; mi++) {
        #pragma unroll
        for (int t = 0; t < 8; t++) {
            int col = (ntBeg + t) * 8 + 2 * qd;
            #pragma unroll
            for (int half = 0; half < 2; half++) {
                int row = m0 + mt + mi * 16 + grp + half * 8;
                if (row >= M) continue;
                size_t base = (size_t)row * HID + col;
                *(float2*)(C + base) = make_float2(acc[mi][t][half * 2], acc[mi][t][half * 2 + 1]);
            }
        }
    }
}

// ======================= edge attention =====================================
__global__ __launch_bounds__(128) void attn_kernel(
    const float* __restrict__ q, const float* __restrict__ k,
    const float* __restrict__ v, const float* __restrict__ skip,
    const float* __restrict__ We, float* __restrict__ out,
    __nv_bfloat16* __restrict__ outhi, __nv_bfloat16* __restrict__ outlo)
{
    __shared__ float we_s[HID * 3];
    int tid = threadIdx.x;
    for (int i = tid; i < HID * 3; i += blockDim.x) we_s[i] = We[i];
    __syncthreads();

    int warp = blockIdx.x * (blockDim.x >> 5) + (tid >> 5);
    if (warp >= N_NODES) return;
    int lane = tid & 31;
    int col  = (lane >> 3) * DH + (lane & 7) * 4;

    float wr[12];
    #pragma unroll
    for (int i = 0; i < 4; i++)
        #pragma unroll
        for (int c = 0; c < 3; c++)
            wr[i * 3 + c] = we_s[3 * (col + i) + c];

    float4 qv = *(const float4*)(q + (size_t)warp * HID + col);
    float m = -INFINITY, ssum = 0.f;
    float ox = 0.f, oy = 0.f, oz = 0.f, ow = 0.f;

    int e0 = g_off[warp], e1 = g_off[warp + 1];
    for (int e = e0; e < e1; e++) {
        int src = g_ssrc[e];
        float a0 = g_sattr[3 * e + 0];
        float a1 = g_sattr[3 * e + 1];
        float a2 = g_sattr[3 * e + 2];
        float4 kv = *(const float4*)(k + (size_t)src * HID + col);
        float4 vv = *(const float4*)(v + (size_t)src * HID + col);
        float ec0 = fmaf(a0, wr[0], fmaf(a1, wr[1],  a2 * wr[2]));
        float ec1 = fmaf(a0, wr[3], fmaf(a1, wr[4],  a2 * wr[5]));
        float ec2 = fmaf(a0, wr[6], fmaf(a1, wr[7],  a2 * wr[8]));
        float ec3 = fmaf(a0, wr[9], fmaf(a1, wr[10], a2 * wr[11]));
        float kx = kv.x + ec0, ky = kv.y + ec1, kz = kv.z + ec2, kw = kv.w + ec3;
        float dot = qv.x * kx + qv.y * ky + qv.z * kz + qv.w * kw;
        dot += __shfl_xor_sync(0xffffffffu, dot, 1);
        dot += __shfl_xor_sync(0xffffffffu, dot, 2);
        dot += __shfl_xor_sync(0xffffffffu, dot, 4);
        float alpha = dot * 0.17677669529663687f;
        float nm = fmaxf(m, alpha);
        float sc = __expf(m - nm);
        float p  = __expf(alpha - nm);
        ssum = ssum * sc + p;
        ox = ox * sc + p * (vv.x + ec0);
        oy = oy * sc + p * (vv.y + ec1);
        oz = oz * sc + p * (vv.z + ec2);
        ow = ow * sc + p * (vv.w + ec3);
        m = nm;
    }
    float inv = 1.0f / fmaxf(ssum, 1e-16f);
    float4 sk = *(const float4*)(skip + (size_t)warp * HID + col);
    float o0 = ox * inv + sk.x, o1 = oy * inv + sk.y;
    float o2 = oz * inv + sk.z, o3 = ow * inv + sk.w;
    size_t base = (size_t)warp * HID + col;
    *(float4*)(out + base) = make_float4(o0, o1, o2, o3);

    float vs[4] = {o0, o1, o2, o3};
    #pragma unroll
    for (int pr = 0; pr < 2; pr++) {
        float v0 = vs[pr * 2], v1 = vs[pr * 2 + 1];
        __nv_bfloat16 h0 = __float2bfloat16(v0);
        __nv_bfloat16 h1 = __float2bfloat16(v1);
        __nv_bfloat162 hh; hh.x = h0; hh.y = h1;
        __nv_bfloat162 ll;
        ll.x = __float2bfloat16(v0 - __bfloat162float(h0));
        ll.y = __float2bfloat16(v1 - __bfloat162float(h1));
        *(__nv_bfloat162*)(outhi + base + pr * 2) = hh;
        *(__nv_bfloat162*)(outlo + base + pr * 2) = ll;
    }
}

// ======================= launch =============================================
static inline void run_mm(cudaStream_t s,
                          const __nv_bfloat16* Ahi, const __nv_bfloat16* Alo,
                          const __nv_bfloat16* Bhi, const __nv_bfloat16* Blo,
                          const float* bias, const float* res,
                          float* C, __nv_bfloat16* Chi, __nv_bfloat16* Clo,
                          int M, int Nout, int act) {
    int grid = (M + 63) / 64;
    mma_gemm<<<grid, 256, MMA_SMEM3, s>>>(Ahi, Alo, Bhi, Blo, bias, res, C, Chi, Clo, M, Nout, act);
}

extern "C" void kernel_launch(void* const* d_in, const int* in_sizes, int n_in,
                              void* d_out, int out_size) {
    const float* x    = (const float*)d_in[0];
    const int*   ei   = (const int*)  d_in[1];
    const float* attr = (const float*)d_in[2];
    const float* Wq1 = (const float*)d_in[3],  *Wk1 = (const float*)d_in[4];
    const float* Wv1 = (const float*)d_in[5],  *We1 = (const float*)d_in[6];
    const float* Ws1 = (const float*)d_in[7];
    const float* M1a = (const float*)d_in[8],  *b1a = (const float*)d_in[9];
    const float* M1b = (const float*)d_in[10], *b1b = (const float*)d_in[11];
    const float* Wq2 = (const float*)d_in[12], *Wk2 = (const float*)d_in[13];
    const float* Wv2 = (const float*)d_in[14], *We2 = (const float*)d_in[15];
    const float* Ws2 = (const float*)d_in[16];
    const float* M2a = (const float*)d_in[17], *b2a = (const float*)d_in[18];
    const float* M2b = (const float*)d_in[19], *b2b = (const float*)d_in[20];
    const float* Wf1 = (const float*)d_in[21], *bf1 = (const float*)d_in[22];
    const float* Wf2 = (const float*)d_in[23], *bf2 = (const float*)d_in[24];
    float* out = (float*)d_out;

    float *q, *k, *v, *sk, *h, *t1, *t2;
    cudaGetSymbolAddress((void**)&q,  g_q);
    cudaGetSymbolAddress((void**)&k,  g_k);
    cudaGetSymbolAddress((void**)&v,  g_v);
    cudaGetSymbolAddress((void**)&sk, g_sk);
    cudaGetSymbolAddress((void**)&h,  g_h);
    cudaGetSymbolAddress((void**)&t1, g_t1);
    cudaGetSymbolAddress((void**)&t2, g_t2);

    __nv_bfloat16 *xhi, *xlo, *hhi, *hlo, *t1hi, *t1lo, *t2hi, *t2lo, *whi, *wlo;
    cudaGetSymbolAddress((void**)&xhi,  g_xhi);
    cudaGetSymbolAddress((void**)&xlo,  g_xlo);
    cudaGetSymbolAddress((void**)&hhi,  g_hhi);
    cudaGetSymbolAddress((void**)&hlo,  g_hlo);
    cudaGetSymbolAddress((void**)&t1hi, g_t1hi);
    cudaGetSymbolAddress((void**)&t1lo, g_t1lo);
    cudaGetSymbolAddress((void**)&t2hi, g_t2hi);
    cudaGetSymbolAddress((void**)&t2lo, g_t2lo);
    cudaGetSymbolAddress((void**)&whi,  g_whi);
    cudaGetSymbolAddress((void**)&wlo,  g_wlo);

    cudaFuncSetAttribute(mma_gemm,  cudaFuncAttributeMaxDynamicSharedMemorySize, MMA_SMEM3);
    cudaFuncSetAttribute(qkvs_gemm, cudaFuncAttributeMaxDynamicSharedMemorySize, MMA_SMEM2);

    // fork/join side stream (created once, outside any capture)
    static cudaStream_t s_side = nullptr;
    static cudaEvent_t ev_fork = nullptr, ev_join = nullptr;
    if (!s_side) {
        cudaStreamCreateWithFlags(&s_side, cudaStreamNonBlocking);
        cudaEventCreateWithFlags(&ev_fork, cudaEventDisableTiming);
        cudaEventCreateWithFlags(&ev_join, cudaEventDisableTiming);
    }

    cudaStream_t s = 0;
    #define WHI(i) (whi + (i) * 16384)
    #define WLO(i) (wlo + (i) * 16384)

    int gblocks = (N_NODES + 127) / 128;
    int ablocks = (N_NODES * 32 + 127) / 128;

    // ---- fork: side stream runs the edge-sort chain concurrently ----
    cudaEventRecord(ev_fork, s);
    cudaStreamWaitEvent(s_side, ev_fork, 0);

    // side(1): zero, side(2): hist
    zero_deg_kernel<<<(N_NODES + 255) / 256, 256, 0, s_side>>>();
    hist_kernel<<<(N_EDGES + 255) / 256, 256, 0, s_side>>>(ei);

    // main(3): bigsplit (weights + x)
    WPtrs wp;
    const float* wsrc[14] = {Wq1, Wk1, Wv1, Ws1, M1a, M1b, Wq2, Wk2, Wv2, Ws2, M2a, M2b, Wf1, Wf2};
    for (int i = 0; i < 14; i++) wp.p[i] = wsrc[i];
    bigsplit_kernel<<<WSPLIT_BLOCKS + XSPLIT_BLOCKS, 256, 0, s>>>(wp, x);

    // main(4): layer-1 fused QKVS GEMM  (ncu capture sentinel)
    QkvsPtrs p1;
    for (int i = 0; i < 4; i++) { p1.bh[i] = WHI(i); p1.bl[i] = WLO(i); }
    p1.c[0] = q; p1.c[1] = k; p1.c[2] = v; p1.c[3] = sk;
    qkvs_gemm<<<dim3(gblocks, 4), 256, MMA_SMEM2, s>>>(xhi, xlo, p1, N_NODES);

    // side(5-8): scans + scatter
    scan_s1<<<SCAN_NBLK, 1024, 0, s_side>>>();
    scan_s2<<<1, 64, 0, s_side>>>();
    scan_s3<<<(N_NODES + 255) / 256, 256, 0, s_side>>>();
    scatter_kernel<<<(N_EDGES + 255) / 256, 256, 0, s_side>>>(ei, attr);

    // ---- join ----
    cudaEventRecord(ev_join, s_side);
    cudaStreamWaitEvent(s, ev_join, 0);

    // layer 1
    attn_kernel<<<ablocks, 128, 0, s>>>(q, k, v, sk, We1, h, hhi, hlo);
    run_mm(s, hhi,  hlo,  WHI(4), WLO(4), b1a, nullptr, t1, t1hi, t1lo, N_NODES, HID, 1);
    run_mm(s, t1hi, t1lo, WHI(5), WLO(5), b1b, h,       t2, t2hi, t2lo, N_NODES, HID, 1);

    // layer 2
    QkvsPtrs p2;
    for (int i = 0; i < 4; i++) { p2.bh[i] = WHI(6 + i); p2.bl[i] = WLO(6 + i); }
    p2.c[0] = q; p2.c[1] = k; p2.c[2] = v; p2.c[3] = sk;
    qkvs_gemm<<<dim3(gblocks, 4), 256, MMA_SMEM2, s>>>(t2hi, t2lo, p2, N_NODES);
    attn_kernel<<<ablocks, 128, 0, s>>>(q, k, v, sk, We2, h, hhi, hlo);
    run_mm(s, hhi,  hlo,  WHI(10), WLO(10), b2a, nullptr, t1, t1hi, t1lo, N_NODES, HID, 1);
    run_mm(s, t1hi, t1lo, WHI(11), WLO(11), b2b, h,       t2, t2hi, t2lo, N_NODES, HID, 1);

    // final MLP
    run_mm(s, t2hi, t2lo, WHI(12), WLO(12), bf1, nullptr, t1, t1hi, t1lo, N_NODES, HID, 1);
    run_mm(s, t1hi, t1lo, WHI(13), WLO(13), bf2, nullptr, out, nullptr, nullptr, N_NODES, OUTD, 1);
}

// round 12
// speedup vs baseline: 1.3278x; 1.0554x over previous
#include <cuda_runtime.h>
#include <cuda_bf16.h>
#include <math.h>
#include <stdint.h>

#define N_NODES 50000
#define N_EDGES 800000
#define HID     128
#define NHEAD   4
#define DH      32
#define OUTD    64

// ======================= scratch (device globals) ===========================
__device__ float g_q [N_NODES * HID];
__device__ float g_k [N_NODES * HID];
__device__ float g_v [N_NODES * HID];
__device__ float g_sk[N_NODES * HID];
__device__ float g_h [N_NODES * HID];
__device__ float g_t1[N_NODES * HID];
__device__ float g_t2[N_NODES * HID];
__device__ int   g_deg [N_NODES];
__device__ int   g_off [N_NODES + 1];
__device__ int   g_cur [N_NODES];
__device__ int   g_ssrc[N_EDGES];
__device__ float g_sattr[N_EDGES * 3];

#define SCAN_NBLK 49
__device__ int g_bsum[SCAN_NBLK];
__device__ int g_bpre[SCAN_NBLK];

__device__ __nv_bfloat16 g_xhi [N_NODES * HID];
__device__ __nv_bfloat16 g_xlo [N_NODES * HID];
__device__ __nv_bfloat16 g_hhi [N_NODES * HID];
__device__ __nv_bfloat16 g_hlo [N_NODES * HID];
__device__ __nv_bfloat16 g_t1hi[N_NODES * HID];
__device__ __nv_bfloat16 g_t1lo[N_NODES * HID];
__device__ __nv_bfloat16 g_t2hi[N_NODES * HID];
__device__ __nv_bfloat16 g_t2lo[N_NODES * HID];
__device__ __nv_bfloat16 g_whi[14 * 16384];
__device__ __nv_bfloat16 g_wlo[14 * 16384];

// ============ fused: weight split + x split (one launch) ====================
struct WPtrs { const float* p[14]; };

#define WSPLIT_BLOCKS 864
#define XSPLIT_BLOCKS 25000

__global__ void bigsplit_kernel(WPtrs wp, const float* __restrict__ x) {
    int b = blockIdx.x;
    if (b < WSPLIT_BLOCKS) {
        int mi, cb;
        if (b < 832) { mi = b >> 6; cb = b & 63; }
        else         { mi = 13;     cb = b - 832; }
        int i = cb * 256 + threadIdx.x;
        int n = (mi == 13) ? 8192 : 16384;
        if (i < n) {
            float v = wp.p[mi][i];
            __nv_bfloat16 h = __float2bfloat16(v);
            g_whi[mi * 16384 + i] = h;
            g_wlo[mi * 16384 + i] = __float2bfloat16(v - __bfloat162float(h));
        }
    } else {
        int i = (b - WSPLIT_BLOCKS) * 256 + threadIdx.x;
        float v = x[i];
        __nv_bfloat16 h = __float2bfloat16(v);
        g_xhi[i] = h;
        g_xlo[i] = __float2bfloat16(v - __bfloat162float(h));
    }
}

// ======================= edge sorting =======================================
__global__ void zero_deg_kernel() {
    int i = blockIdx.x * blockDim.x + threadIdx.x;
    if (i < N_NODES) g_deg[i] = 0;
}

__global__ void hist_kernel(const int* __restrict__ ei) {
    int e = blockIdx.x * blockDim.x + threadIdx.x;
    if (e < N_EDGES) atomicAdd(&g_deg[ei[N_EDGES + e]], 1);
}

__global__ __launch_bounds__(1024) void scan_s1() {
    __shared__ int wsum[32];
    int tid = threadIdx.x, lane = tid & 31, wid = tid >> 5;
    int i = blockIdx.x * 1024 + tid;
    int v = (i < N_NODES) ? g_deg[i] : 0;
    int x = v;
    #pragma unroll
    for (int d = 1; d < 32; d <<= 1) {
        int y = __shfl_up_sync(0xffffffffu, x, d);
        if (lane >= d) x += y;
    }
    if (lane == 31) wsum[wid] = x;
    __syncthreads();
    if (wid == 0) {
        int s = wsum[lane];
        #pragma unroll
        for (int d = 1; d < 32; d <<= 1) {
            int y = __shfl_up_sync(0xffffffffu, s, d);
            if (lane >= d) s += y;
        }
        wsum[lane] = s;
    }
    __syncthreads();
    int incl = x + (wid > 0 ? wsum[wid - 1] : 0);
    if (i < N_NODES) g_off[i] = incl - v;
    if (tid == 1023) g_bsum[blockIdx.x] = incl;
}

__global__ void scan_s2() {
    __shared__ int w0sum;
    int tid = threadIdx.x;
    int lane = tid & 31, wid = tid >> 5;
    int v = (tid < SCAN_NBLK) ? g_bsum[tid] : 0;
    int x = v;
    #pragma unroll
    for (int d = 1; d < 32; d <<= 1) {
        int y = __shfl_up_sync(0xffffffffu, x, d);
        if (lane >= d) x += y;
    }
    if (wid == 0 && lane == 31) w0sum = x;
    __syncthreads();
    int incl = x + (wid ? w0sum : 0);
    if (tid < SCAN_NBLK) g_bpre[tid] = incl - v;
    if (tid == SCAN_NBLK - 1) g_off[N_NODES] = incl;
}

__global__ void scan_s3() {
    int i = blockIdx.x * blockDim.x + threadIdx.x;
    if (i < N_NODES) {
        int o = g_off[i] + g_bpre[i >> 10];
        g_off[i] = o;
        g_cur[i] = o;
    }
}

__global__ void scatter_kernel(const int* __restrict__ ei, const float* __restrict__ attr) {
    int e = blockIdx.x * blockDim.x + threadIdx.x;
    if (e < N_EDGES) {
        int dst = ei[N_EDGES + e];
        int pos = atomicAdd(&g_cur[dst], 1);
        g_ssrc[pos] = ei[e];
        g_sattr[3 * pos + 0] = attr[3 * e + 0];
        g_sattr[3 * pos + 1] = attr[3 * e + 1];
        g_sattr[3 * pos + 2] = attr[3 * e + 2];
    }
}

// ======================= GELU ==============================================
__device__ __forceinline__ float gelu_f(float x) {
    float x3 = x * x * x;
    float u = 0.7978845608028654f * (x + 0.044715f * x3);
    return 0.5f * x * (1.0f + tanhf(u));
}

// ======================= HMMA GEMM common ===================================
#define SROW2 72

__device__ __forceinline__ void mma16816(float* c,
    uint32_t a0, uint32_t a1, uint32_t a2, uint32_t a3,
    uint32_t b0, uint32_t b1) {
    asm volatile(
        "mma.sync.aligned.m16n8k16.row.col.f32.bf16.bf16.f32 "
        "{%0,%1,%2,%3}, {%4,%5,%6,%7}, {%8,%9}, {%0,%1,%2,%3};"
        : "+f"(c[0]), "+f"(c[1]), "+f"(c[2]), "+f"(c[3])
        : "r"(a0), "r"(a1), "r"(a2), "r"(a3), "r"(b0), "r"(b1));
}

__device__ __forceinline__ void ldsm_x4(uint32_t& r0, uint32_t& r1,
                                        uint32_t& r2, uint32_t& r3, uint32_t addr) {
    asm volatile("ldmatrix.sync.aligned.m8n8.x4.shared.b16 {%0,%1,%2,%3}, [%4];"
                 : "=r"(r0), "=r"(r1), "=r"(r2), "=r"(r3) : "r"(addr));
}

__device__ __forceinline__ uint32_t smem_u32(const void* p) {
    return (uint32_t)__cvta_generic_to_shared(p);
}

__device__ __forceinline__ void stage_slab_A128(
    const __nv_bfloat16* Ahi, const __nv_bfloat16* Alo,
    __nv_bfloat16* sAh, __nv_bfloat16* sAl, int m0, int M, int slab, int tid)
{
    int row = tid >> 1;
    int u0  = (tid & 1) * 4;
    int gr  = m0 + row;
    bool ok = gr < M;
    const uint4* ah = (const uint4*)(Ahi + (size_t)gr * 128 + slab * 64);
    const uint4* al = (const uint4*)(Alo + (size_t)gr * 128 + slab * 64);
    uint4 z = make_uint4(0u, 0u, 0u, 0u);
    #pragma unroll
    for (int u = u0; u < u0 + 4; u++) {
        *(uint4*)(&sAh[row * SROW2 + u * 8]) = ok ? ah[u] : z;
        *(uint4*)(&sAl[row * SROW2 + u * 8]) = ok ? al[u] : z;
    }
}

__device__ __forceinline__ void stage_slab_A64(
    const __nv_bfloat16* Ahi, const __nv_bfloat16* Alo,
    __nv_bfloat16* sAh, __nv_bfloat16* sAl, int m0, int M, int slab, int tid)
{
    int row = tid >> 2;
    int u0  = (tid & 3) * 2;
    int gr  = m0 + row;
    bool ok = gr < M;
    const uint4* ah = (const uint4*)(Ahi + (size_t)gr * 128 + slab * 64);
    const uint4* al = (const uint4*)(Alo + (size_t)gr * 128 + slab * 64);
    uint4 z = make_uint4(0u, 0u, 0u, 0u);
    #pragma unroll
    for (int u = u0; u < u0 + 2; u++) {
        *(uint4*)(&sAh[row * SROW2 + u * 8]) = ok ? ah[u] : z;
        *(uint4*)(&sAl[row * SROW2 + u * 8]) = ok ? al[u] : z;
    }
}

__device__ __forceinline__ void stage_slab_B(
    const __nv_bfloat16* Bhi, const __nv_bfloat16* Blo,
    __nv_bfloat16* sBh, __nv_bfloat16* sBl, int Nout, int slab, int tid)
{
    int row = tid >> 1;
    if (row < Nout) {
        int u0 = (tid & 1) * 4;
        const uint4* bh = (const uint4*)(Bhi + (size_t)row * 128 + slab * 64);
        const uint4* bl = (const uint4*)(Blo + (size_t)row * 128 + slab * 64);
        #pragma unroll
        for (int u = u0; u < u0 + 4; u++) {
            *(uint4*)(&sBh[row * SROW2 + u * 8]) = bh[u];
            *(uint4*)(&sBl[row * SROW2 + u * 8]) = bl[u];
        }
    }
}

__device__ __forceinline__ void mainloop_slab(
    const __nv_bfloat16* sAh, const __nv_bfloat16* sAl,
    const __nv_bfloat16* sBh, const __nv_bfloat16* sBl,
    float acc[2][8][4], int mt, int lane, int ntBeg, int ntN)
{
    uint32_t aAh = smem_u32(sAh), aAl = smem_u32(sAl);
    uint32_t aBh = smem_u32(sBh), aBl = smem_u32(sBl);
    int arow = lane & 15, akh = 8 * (lane >> 4);
    int brow = lane & 7;
    int bsel = lane >> 4;
    int bk   = 8 * ((lane >> 3) & 1);

    for (int kt = 0; kt < 64; kt += 16) {
        uint32_t ah[2][4], al[2][4];
        #pragma unroll
        for (int mi = 0; mi < 2; mi++) {
            int aoff = (mt + mi * 16 + arow) * SROW2 + akh + kt;
            ldsm_x4(ah[mi][0], ah[mi][1], ah[mi][2], ah[mi][3], aAh + (uint32_t)aoff * 2);
            ldsm_x4(al[mi][0], al[mi][1], al[mi][2], al[mi][3], aAl + (uint32_t)aoff * 2);
        }
        #pragma unroll
        for (int p = 0; p < 4; p++) {
            if (2 * p >= ntN) break;
            int nt = ntBeg + 2 * p + bsel;
            int boff = (nt * 8 + brow) * SROW2 + bk + kt;
            uint32_t bh0, bh1, bh2, bh3, bl0, bl1, bl2, bl3;
            ldsm_x4(bh0, bh1, bh2, bh3, aBh + (uint32_t)boff * 2);
            ldsm_x4(bl0, bl1, bl2, bl3, aBl + (uint32_t)boff * 2);
            #pragma unroll
            for (int mi = 0; mi < 2; mi++) {
                mma16816(acc[mi][2 * p + 0], ah[mi][0], ah[mi][1], ah[mi][2], ah[mi][3], bh0, bh1);
                mma16816(acc[mi][2 * p + 0], ah[mi][0], ah[mi][1], ah[mi][2], ah[mi][3], bl0, bl1);
                mma16816(acc[mi][2 * p + 0], al[mi][0], al[mi][1], al[mi][2], al[mi][3], bh0, bh1);
                mma16816(acc[mi][2 * p + 1], ah[mi][0], ah[mi][1], ah[mi][2], ah[mi][3], bh2, bh3);
                mma16816(acc[mi][2 * p + 1], ah[mi][0], ah[mi][1], ah[mi][2], ah[mi][3], bl2, bl3);
                mma16816(acc[mi][2 * p + 1], al[mi][0], al[mi][1], al[mi][2], al[mi][3], bh2, bh3);
            }
        }
    }
}

// ======================= mma_gemm: 64-row CTAs ==============================
#define OFF3_AH 0
#define OFF3_AL 9216
#define OFF3_BH 18432
#define OFF3_BL 36864
#define MMA_SMEM3 55296

__global__ __launch_bounds__(256, 2) void mma_gemm(
    const __nv_bfloat16* __restrict__ Ahi, const __nv_bfloat16* __restrict__ Alo,
    const __nv_bfloat16* __restrict__ Bhi, const __nv_bfloat16* __restrict__ Blo,
    const float* __restrict__ bias, const float* __restrict__ res,
    float* __restrict__ C, __nv_bfloat16* __restrict__ Chi, __nv_bfloat16* __restrict__ Clo,
    int M, int Nout, int act)
{
    extern __shared__ char smem[];
    __nv_bfloat16* sAh = (__nv_bfloat16*)(smem + OFF3_AH);
    __nv_bfloat16* sAl = (__nv_bfloat16*)(smem + OFF3_AL);
    __nv_bfloat16* sBh = (__nv_bfloat16*)(smem + OFF3_BH);
    __nv_bfloat16* sBl = (__nv_bfloat16*)(smem + OFF3_BL);
    int tid = threadIdx.x;
    int m0 = blockIdx.x * 64;

    int lane = tid & 31, wid = tid >> 5;
    int grp = lane >> 2, qd = lane & 3;
    int mt = (wid >> 2) * 32;
    int NT = Nout >> 3;
    int ntBeg = (wid & 3) * (NT >> 2);
    int ntN   = NT >> 2;

    float acc[2][8][4];
    #pragma unroll
    for (int mi = 0; mi < 2; mi++)
        #pragma unroll
        for (int i = 0; i < 8; i++)
            #pragma unroll
            for (int j = 0; j < 4; j++) acc[mi][i][j] = 0.f;

    #pragma unroll
    for (int s = 0; s < 2; s++) {
        if (s) __syncthreads();
        stage_slab_A64(Ahi, Alo, sAh, sAl, m0, M, s, tid);
        stage_slab_B(Bhi, Blo, sBh, sBl, Nout, s, tid);
        __syncthreads();
        mainloop_slab(sAh, sAl, sBh, sBl, acc, mt, lane, ntBeg, ntN);
    }

    #pragma unroll
    for (int mi = 0; mi < 2; mi++) {
        #pragma unroll
        for (int t = 0; t < 8; t++) {
            if (t >= ntN) break;
            int col = (ntBeg + t) * 8 + 2 * qd;
            float bsum0 = bias ? bias[col]     : 0.f;
            float bsum1 = bias ? bias[col + 1] : 0.f;
            #pragma unroll
            for (int half = 0; half < 2; half++) {
                int row = m0 + mt + mi * 16 + grp + half * 8;
                if (row >= M) continue;
                float v0 = acc[mi][t][half * 2 + 0] + bsum0;
                float v1 = acc[mi][t][half * 2 + 1] + bsum1;
                if (act) { v0 = gelu_f(v0); v1 = gelu_f(v1); }
                size_t base = (size_t)row * Nout + col;
                if (res) { v0 += res[base]; v1 += res[base + 1]; }
                *(float2*)(C + base) = make_float2(v0, v1);
                if (Chi) {
                    __nv_bfloat16 h0 = __float2bfloat16(v0);
                    __nv_bfloat16 h1 = __float2bfloat16(v1);
                    __nv_bfloat162 hh; hh.x = h0; hh.y = h1;
                    __nv_bfloat162 ll;
                    ll.x = __float2bfloat16(v0 - __bfloat162float(h0));
                    ll.y = __float2bfloat16(v1 - __bfloat162float(h1));
                    *(__nv_bfloat162*)(Chi + base) = hh;
                    *(__nv_bfloat162*)(Clo + base) = ll;
                }
            }
        }
    }
}

// ======================= qkvs_gemm: 128-row CTAs, 2 CTAs/SM =================
#define OFF2_AH 0
#define OFF2_AL 18432
#define OFF2_BH 36864
#define OFF2_BL 55296
#define MMA_SMEM2 73728

struct QkvsPtrs {
    const __nv_bfloat16 *bh[4], *bl[4];
    float* c[4];
};

__global__ __launch_bounds__(256, 2) void qkvs_gemm(
    const __nv_bfloat16* __restrict__ Ahi, const __nv_bfloat16* __restrict__ Alo,
    QkvsPtrs pp, int M)
{
    extern __shared__ char smem[];
    __nv_bfloat16* sAh = (__nv_bfloat16*)(smem + OFF2_AH);
    __nv_bfloat16* sAl = (__nv_bfloat16*)(smem + OFF2_AL);
    __nv_bfloat16* sBh = (__nv_bfloat16*)(smem + OFF2_BH);
    __nv_bfloat16* sBl = (__nv_bfloat16*)(smem + OFF2_BL);
    int tid = threadIdx.x;
    int m0 = blockIdx.x * 128;
    int sel = blockIdx.y;

    int lane = tid & 31, wid = tid >> 5;
    int grp = lane >> 2, qd = lane & 3;
    int mt = (wid >> 1) * 32;
    int ntBeg = (wid & 1) * 8;

    float acc[2][8][4];
    #pragma unroll
    for (int mi = 0; mi < 2; mi++)
        #pragma unroll
        for (int i = 0; i < 8; i++)
            #pragma unroll
            for (int j = 0; j < 4; j++) acc[mi][i][j] = 0.f;

    #pragma unroll
    for (int s = 0; s < 2; s++) {
        if (s) __syncthreads();
        stage_slab_A128(Ahi, Alo, sAh, sAl, m0, M, s, tid);
        stage_slab_B(pp.bh[sel], pp.bl[sel], sBh, sBl, HID, s, tid);
        __syncthreads();
        mainloop_slab(sAh, sAl, sBh, sBl, acc, mt, lane, ntBeg, 8);
    }

    float* C = pp.c[sel];
    #pragma unroll
    for (int mi = 0; mi < 2; mi++) {
        #pragma unroll
        for (int t = 0; t < 8; t++) {
            int col = (ntBeg + t) * 8 + 2 * qd;
            #pragma unroll
            for (int half = 0; half < 2; half++) {
                int row = m0 + mt + mi * 16 + grp + half * 8;
                if (row >= M) continue;
                size_t base = (size_t)row * HID + col;
                *(float2*)(C + base) = make_float2(acc[mi][t][half * 2], acc[mi][t][half * 2 + 1]);
            }
        }
    }
}

// ======= edge attention: DUAL independent online-softmax accumulators =======
__global__ __launch_bounds__(128) void attn_kernel(
    const float* __restrict__ q, const float* __restrict__ k,
    const float* __restrict__ v, const float* __restrict__ skip,
    const float* __restrict__ We, float* __restrict__ out,
    __nv_bfloat16* __restrict__ outhi, __nv_bfloat16* __restrict__ outlo)
{
    __shared__ float we_s[HID * 3];
    int tid = threadIdx.x;
    for (int i = tid; i < HID * 3; i += blockDim.x) we_s[i] = We[i];
    __syncthreads();

    int warp = blockIdx.x * (blockDim.x >> 5) + (tid >> 5);
    if (warp >= N_NODES) return;
    int lane = tid & 31;
    int col  = (lane >> 3) * DH + (lane & 7) * 4;

    float wr[12];
    #pragma unroll
    for (int i = 0; i < 4; i++)
        #pragma unroll
        for (int c = 0; c < 3; c++)
            wr[i * 3 + c] = we_s[3 * (col + i) + c];

    float4 qv = *(const float4*)(q + (size_t)warp * HID + col);

    // two independent accumulators
    float mA = -INFINITY, sA = 0.f, oAx = 0.f, oAy = 0.f, oAz = 0.f, oAw = 0.f;
    float mB = -INFINITY, sB = 0.f, oBx = 0.f, oBy = 0.f, oBz = 0.f, oBw = 0.f;

    int e0 = g_off[warp], e1 = g_off[warp + 1];
    int e = e0;
    for (; e + 2 <= e1; e += 2) {
        // front-batched loads for both edges
        int s0 = g_ssrc[e], s1 = g_ssrc[e + 1];
        float a00 = g_sattr[3 * e + 0], a01 = g_sattr[3 * e + 1], a02 = g_sattr[3 * e + 2];
        float a10 = g_sattr[3 * e + 3], a11 = g_sattr[3 * e + 4], a12 = g_sattr[3 * e + 5];
        float4 kv0 = *(const float4*)(k + (size_t)s0 * HID + col);
        float4 vv0 = *(const float4*)(v + (size_t)s0 * HID + col);
        float4 kv1 = *(const float4*)(k + (size_t)s1 * HID + col);
        float4 vv1 = *(const float4*)(v + (size_t)s1 * HID + col);

        // edge-attr projections
        float e00 = fmaf(a00, wr[0], fmaf(a01, wr[1],  a02 * wr[2]));
        float e01 = fmaf(a00, wr[3], fmaf(a01, wr[4],  a02 * wr[5]));
        float e02 = fmaf(a00, wr[6], fmaf(a01, wr[7],  a02 * wr[8]));
        float e03 = fmaf(a00, wr[9], fmaf(a01, wr[10], a02 * wr[11]));
        float e10 = fmaf(a10, wr[0], fmaf(a11, wr[1],  a12 * wr[2]));
        float e11 = fmaf(a10, wr[3], fmaf(a11, wr[4],  a12 * wr[5]));
        float e12 = fmaf(a10, wr[6], fmaf(a11, wr[7],  a12 * wr[8]));
        float e13 = fmaf(a10, wr[9], fmaf(a11, wr[10], a12 * wr[11]));

        // dots (independent)
        float d0 = qv.x * (kv0.x + e00) + qv.y * (kv0.y + e01)
                 + qv.z * (kv0.z + e02) + qv.w * (kv0.w + e03);
        float d1 = qv.x * (kv1.x + e10) + qv.y * (kv1.y + e11)
                 + qv.z * (kv1.z + e12) + qv.w * (kv1.w + e13);
        // interleaved butterflies (independent chains)
        d0 += __shfl_xor_sync(0xffffffffu, d0, 1);
        d1 += __shfl_xor_sync(0xffffffffu, d1, 1);
        d0 += __shfl_xor_sync(0xffffffffu, d0, 2);
        d1 += __shfl_xor_sync(0xffffffffu, d1, 2);
        d0 += __shfl_xor_sync(0xffffffffu, d0, 4);
        d1 += __shfl_xor_sync(0xffffffffu, d1, 4);
        float al0 = d0 * 0.17677669529663687f;
        float al1 = d1 * 0.17677669529663687f;

        // accumulator A <- edge e  (independent of B)
        {
            float nm = fmaxf(mA, al0);
            float sc = __expf(mA - nm);
            float p  = __expf(al0 - nm);
            sA = sA * sc + p;
            oAx = oAx * sc + p * (vv0.x + e00);
            oAy = oAy * sc + p * (vv0.y + e01);
            oAz = oAz * sc + p * (vv0.z + e02);
            oAw = oAw * sc + p * (vv0.w + e03);
            mA = nm;
        }
        // accumulator B <- edge e+1
        {
            float nm = fmaxf(mB, al1);
            float sc = __expf(mB - nm);
            float p  = __expf(al1 - nm);
            sB = sB * sc + p;
            oBx = oBx * sc + p * (vv1.x + e10);
            oBy = oBy * sc + p * (vv1.y + e11);
            oBz = oBz * sc + p * (vv1.z + e12);
            oBw = oBw * sc + p * (vv1.w + e13);
            mB = nm;
        }
    }
    // remainder edge -> A
    if (e < e1) {
        int src = g_ssrc[e];
        float a0 = g_sattr[3 * e + 0];
        float a1 = g_sattr[3 * e + 1];
        float a2 = g_sattr[3 * e + 2];
        float4 kv = *(const float4*)(k + (size_t)src * HID + col);
        float4 vv = *(const float4*)(v + (size_t)src * HID + col);
        float ec0 = fmaf(a0, wr[0], fmaf(a1, wr[1],  a2 * wr[2]));
        float ec1 = fmaf(a0, wr[3], fmaf(a1, wr[4],  a2 * wr[5]));
        float ec2 = fmaf(a0, wr[6], fmaf(a1, wr[7],  a2 * wr[8]));
        float ec3 = fmaf(a0, wr[9], fmaf(a1, wr[10], a2 * wr[11]));
        float dot = qv.x * (kv.x + ec0) + qv.y * (kv.y + ec1)
                  + qv.z * (kv.z + ec2) + qv.w * (kv.w + ec3);
        dot += __shfl_xor_sync(0xffffffffu, dot, 1);
        dot += __shfl_xor_sync(0xffffffffu, dot, 2);
        dot += __shfl_xor_sync(0xffffffffu, dot, 4);
        float alpha = dot * 0.17677669529663687f;
        float nm = fmaxf(mA, alpha);
        float sc = __expf(mA - nm);
        float p  = __expf(alpha - nm);
        sA = sA * sc + p;
        oAx = oAx * sc + p * (vv.x + ec0);
        oAy = oAy * sc + p * (vv.y + ec1);
        oAz = oAz * sc + p * (vv.z + ec2);
        oAw = oAw * sc + p * (vv.w + ec3);
        mA = nm;
    }

    // merge B into A (exact)
    {
        float nm = fmaxf(mA, mB);
        // guard: if both -inf (no edges), weights are 0 anyway
        float wa = (mA == -INFINITY) ? 0.f : __expf(mA - nm);
        float wb = (mB == -INFINITY) ? 0.f : __expf(mB - nm);
        sA = sA * wa + sB * wb;
        oAx = oAx * wa + oBx * wb;
        oAy = oAy * wa + oBy * wb;
        oAz = oAz * wa + oBz * wb;
        oAw = oAw * wa + oBw * wb;
    }

    float inv = 1.0f / fmaxf(sA, 1e-16f);
    float4 sk = *(const float4*)(skip + (size_t)warp * HID + col);
    float o0 = oAx * inv + sk.x, o1 = oAy * inv + sk.y;
    float o2 = oAz * inv + sk.z, o3 = oAw * inv + sk.w;
    size_t base = (size_t)warp * HID + col;
    *(float4*)(out + base) = make_float4(o0, o1, o2, o3);

    float vs[4] = {o0, o1, o2, o3};
    #pragma unroll
    for (int pr = 0; pr < 2; pr++) {
        float v0 = vs[pr * 2], v1 = vs[pr * 2 + 1];
        __nv_bfloat16 h0 = __float2bfloat16(v0);
        __nv_bfloat16 h1 = __float2bfloat16(v1);
        __nv_bfloat162 hh; hh.x = h0; hh.y = h1;
        __nv_bfloat162 ll;
        ll.x = __float2bfloat16(v0 - __bfloat162float(h0));
        ll.y = __float2bfloat16(v1 - __bfloat162float(h1));
        *(__nv_bfloat162*)(outhi + base + pr * 2) = hh;
        *(__nv_bfloat162*)(outlo + base + pr * 2) = ll;
    }
}

// ======================= launch =============================================
static inline void run_mm(cudaStream_t s,
                          const __nv_bfloat16* Ahi, const __nv_bfloat16* Alo,
                          const __nv_bfloat16* Bhi, const __nv_bfloat16* Blo,
                          const float* bias, const float* res,
                          float* C, __nv_bfloat16* Chi, __nv_bfloat16* Clo,
                          int M, int Nout, int act) {
    int grid = (M + 63) / 64;
    mma_gemm<<<grid, 256, MMA_SMEM3, s>>>(Ahi, Alo, Bhi, Blo, bias, res, C, Chi, Clo, M, Nout, act);
}

extern "C" void kernel_launch(void* const* d_in, const int* in_sizes, int n_in,
                              void* d_out, int out_size) {
    const float* x    = (const float*)d_in[0];
    const int*   ei   = (const int*)  d_in[1];
    const float* attr = (const float*)d_in[2];
    const float* Wq1 = (const float*)d_in[3],  *Wk1 = (const float*)d_in[4];
    const float* Wv1 = (const float*)d_in[5],  *We1 = (const float*)d_in[6];
    const float* Ws1 = (const float*)d_in[7];
    const float* M1a = (const float*)d_in[8],  *b1a = (const float*)d_in[9];
    const float* M1b = (const float*)d_in[10], *b1b = (const float*)d_in[11];
    const float* Wq2 = (const float*)d_in[12], *Wk2 = (const float*)d_in[13];
    const float* Wv2 = (const float*)d_in[14], *We2 = (const float*)d_in[15];
    const float* Ws2 = (const float*)d_in[16];
    const float* M2a = (const float*)d_in[17], *b2a = (const float*)d_in[18];
    const float* M2b = (const float*)d_in[19], *b2b = (const float*)d_in[20];
    const float* Wf1 = (const float*)d_in[21], *bf1 = (const float*)d_in[22];
    const float* Wf2 = (const float*)d_in[23], *bf2 = (const float*)d_in[24];
    float* out = (float*)d_out;

    float *q, *k, *v, *sk, *h, *t1, *t2;
    cudaGetSymbolAddress((void**)&q,  g_q);
    cudaGetSymbolAddress((void**)&k,  g_k);
    cudaGetSymbolAddress((void**)&v,  g_v);
    cudaGetSymbolAddress((void**)&sk, g_sk);
    cudaGetSymbolAddress((void**)&h,  g_h);
    cudaGetSymbolAddress((void**)&t1, g_t1);
    cudaGetSymbolAddress((void**)&t2, g_t2);

    __nv_bfloat16 *xhi, *xlo, *hhi, *hlo, *t1hi, *t1lo, *t2hi, *t2lo, *whi, *wlo;
    cudaGetSymbolAddress((void**)&xhi,  g_xhi);
    cudaGetSymbolAddress((void**)&xlo,  g_xlo);
    cudaGetSymbolAddress((void**)&hhi,  g_hhi);
    cudaGetSymbolAddress((void**)&hlo,  g_hlo);
    cudaGetSymbolAddress((void**)&t1hi, g_t1hi);
    cudaGetSymbolAddress((void**)&t1lo, g_t1lo);
    cudaGetSymbolAddress((void**)&t2hi, g_t2hi);
    cudaGetSymbolAddress((void**)&t2lo, g_t2lo);
    cudaGetSymbolAddress((void**)&whi,  g_whi);
    cudaGetSymbolAddress((void**)&wlo,  g_wlo);

    cudaFuncSetAttribute(mma_gemm,  cudaFuncAttributeMaxDynamicSharedMemorySize, MMA_SMEM3);
    cudaFuncSetAttribute(qkvs_gemm, cudaFuncAttributeMaxDynamicSharedMemorySize, MMA_SMEM2);

    static cudaStream_t s_side = nullptr;
    static cudaEvent_t ev_fork = nullptr, ev_join = nullptr;
    if (!s_side) {
        cudaStreamCreateWithFlags(&s_side, cudaStreamNonBlocking);
        cudaEventCreateWithFlags(&ev_fork, cudaEventDisableTiming);
        cudaEventCreateWithFlags(&ev_join, cudaEventDisableTiming);
    }

    cudaStream_t s = 0;
    #define WHI(i) (whi + (i) * 16384)
    #define WLO(i) (wlo + (i) * 16384)

    int gblocks = (N_NODES + 127) / 128;
    int ablocks = (N_NODES * 32 + 127) / 128;

    // ---- fork: side stream runs the edge-sort chain concurrently ----
    cudaEventRecord(ev_fork, s);
    cudaStreamWaitEvent(s_side, ev_fork, 0);

    zero_deg_kernel<<<(N_NODES + 255) / 256, 256, 0, s_side>>>();
    hist_kernel<<<(N_EDGES + 255) / 256, 256, 0, s_side>>>(ei);

    WPtrs wp;
    const float* wsrc[14] = {Wq1, Wk1, Wv1, Ws1, M1a, M1b, Wq2, Wk2, Wv2, Ws2, M2a, M2b, Wf1, Wf2};
    for (int i = 0; i < 14; i++) wp.p[i] = wsrc[i];
    bigsplit_kernel<<<WSPLIT_BLOCKS + XSPLIT_BLOCKS, 256, 0, s>>>(wp, x);

    // layer-1 fused QKVS GEMM (ncu capture sentinel)
    QkvsPtrs p1;
    for (int i = 0; i < 4; i++) { p1.bh[i] = WHI(i); p1.bl[i] = WLO(i); }
    p1.c[0] = q; p1.c[1] = k; p1.c[2] = v; p1.c[3] = sk;
    qkvs_gemm<<<dim3(gblocks, 4), 256, MMA_SMEM2, s>>>(xhi, xlo, p1, N_NODES);

    scan_s1<<<SCAN_NBLK, 1024, 0, s_side>>>();
    scan_s2<<<1, 64, 0, s_side>>>();
    scan_s3<<<(N_NODES + 255) / 256, 256, 0, s_side>>>();
    scatter_kernel<<<(N_EDGES + 255) / 256, 256, 0, s_side>>>(ei, attr);

    cudaEventRecord(ev_join, s_side);
    cudaStreamWaitEvent(s, ev_join, 0);

    // layer 1
    attn_kernel<<<ablocks, 128, 0, s>>>(q, k, v, sk, We1, h, hhi, hlo);
    run_mm(s, hhi,  hlo,  WHI(4), WLO(4), b1a, nullptr, t1, t1hi, t1lo, N_NODES, HID, 1);
    run_mm(s, t1hi, t1lo, WHI(5), WLO(5), b1b, h,       t2, t2hi, t2lo, N_NODES, HID, 1);

    // layer 2
    QkvsPtrs p2;
    for (int i = 0; i < 4; i++) { p2.bh[i] = WHI(6 + i); p2.bl[i] = WLO(6 + i); }
    p2.c[0] = q; p2.c[1] = k; p2.c[2] = v; p2.c[3] = sk;
    qkvs_gemm<<<dim3(gblocks, 4), 256, MMA_SMEM2, s>>>(t2hi, t2lo, p2, N_NODES);
    attn_kernel<<<ablocks, 128, 0, s>>>(q, k, v, sk, We2, h, hhi, hlo);
    run_mm(s, hhi,  hlo,  WHI(10), WLO(10), b2a, nullptr, t1, t1hi, t1lo, N_NODES, HID, 1);
    run_mm(s, t1hi, t1lo, WHI(11), WLO(11), b2b, h,       t2, t2hi, t2lo, N_NODES, HID, 1);

    // final MLP
    run_mm(s, t2hi, t2lo, WHI(12), WLO(12), bf1, nullptr, t1, t1hi, t1lo, N_NODES, HID, 1);
    run_mm(s, t1hi, t1lo, WHI(13), WLO(13), bf2, nullptr, out, nullptr, nullptr, N_NODES, OUTD, 1);
}